// round 10
// baseline (speedup 1.0000x reference)
#include <cuda_runtime.h>
#include <cuda_bf16.h>
#include <cstdint>
#include <math.h>

#define N_DRUGS 4096
#define N_GENE  5414
#define N_KG    9510
#define N_KG_PAD 9600
#define N_MOL   131072
#define E_MOL_C 524288
#define E_KG_C  524288
#define R_REL   8
#define MLP_IN  1024
#define MLP_H   512
#define DFEAT   256
#define GCN_IN  64
#define GCN_H   128
#define DIM1    256
#define DIM2    128
#define DIM3    64
#define EPSV    1e-5f
#define NKEY_KG (N_KG * R_REL)

// ---------------- scratch ----------------
__device__ __align__(16) float g_h1[N_DRUGS * MLP_H];
__device__ __align__(16) float g_fp[N_DRUGS * DFEAT];
__device__ __align__(16) float g_bufA[(long)N_MOL * DFEAT];
__device__ __align__(16) float g_bufB[(long)N_MOL * DFEAT];
__device__ __align__(16) float g_bufC[(long)N_MOL * DFEAT];
__device__ __align__(16) float g_dinv[N_MOL];
__device__ __align__(16) float g_pool[N_DRUGS * DFEAT];
__device__ __align__(16) float g_xkg[N_KG * DFEAT];
__device__ __align__(16) float g_hr[(long)R_REL * N_KG * DFEAT];   // also AGG [N_KG, 2048]
__device__ __align__(16) float g_agg[N_KG * DFEAT];
__device__ __align__(16) float g_x3[N_KG * DIM3];
__device__ __align__(16) float g_stats[7 * 2048];
// bf16 split operand buffers
__device__ __align__(16) __nv_bfloat16 g_asplit[(long)N_KG_PAD * 6144];
__device__ __align__(16) __nv_bfloat16 g_bsplit[2 * 1024 * 1024];
// CSR scratch
__device__ int g_hist_mol[N_MOL];
__device__ int g_base_mol[N_MOL + 1];
__device__ int g_off_mol[N_MOL];
__device__ int g_ssrc_mol[E_MOL_C];
__device__ int g_hist_kg[NKEY_KG];
__device__ int g_base_kg[NKEY_KG + 1];
__device__ int g_off_kg[NKEY_KG];
__device__ int g_ssrc_kg[E_KG_C];
__device__ int g_bsum[64];
__device__ int g_boff[65];

// ---------------- warp-MMA helpers (baseline PTX, sm_80+) ----------------
__device__ __forceinline__ uint32_t smem_to_u32(const void* p) {
    uint32_t a;
    asm("{ .reg .u64 t; cvta.to.shared.u64 t, %1; cvt.u32.u64 %0, t; }" : "=r"(a) : "l"(p));
    return a;
}
__device__ __forceinline__ void ldmatrix_x4(uint32_t* r, uint32_t addr) {
    asm volatile("ldmatrix.sync.aligned.m8n8.x4.shared.b16 {%0,%1,%2,%3}, [%4];"
                 : "=r"(r[0]), "=r"(r[1]), "=r"(r[2]), "=r"(r[3]) : "r"(addr));
}
__device__ __forceinline__ void mma_bf16(float* d, const uint32_t* a, uint32_t b0, uint32_t b1) {
    asm volatile("mma.sync.aligned.m16n8k16.row.col.f32.bf16.bf16.f32 "
                 "{%0,%1,%2,%3}, {%4,%5,%6,%7}, {%8,%9}, {%0,%1,%2,%3};"
                 : "+f"(d[0]), "+f"(d[1]), "+f"(d[2]), "+f"(d[3])
                 : "r"(a[0]), "r"(a[1]), "r"(a[2]), "r"(a[3]), "r"(b0), "r"(b1));
}

// ---------------- fp32x2 / misc helpers ----------------
__device__ __forceinline__ unsigned long long ffma2(unsigned long long a, unsigned long long b,
                                                    unsigned long long c) {
    unsigned long long d;
    asm("fma.rn.f32x2 %0, %1, %2, %3;" : "=l"(d) : "l"(a), "l"(b), "l"(c));
    return d;
}
__device__ __forceinline__ unsigned long long bcast2(float x) {
    unsigned long long d;
    unsigned r = __float_as_uint(x);
    asm("mov.b64 %0, {%1, %1};" : "=l"(d) : "r"(r));
    return d;
}
__device__ __forceinline__ float4 abn_apply4(float4 v, const float* m, const float* r, int k) {
    v.x = fmaxf((v.x - m[k + 0]) * r[k + 0], 0.f);
    v.y = fmaxf((v.y - m[k + 1]) * r[k + 1], 0.f);
    v.z = fmaxf((v.z - m[k + 2]) * r[k + 2], 0.f);
    v.w = fmaxf((v.w - m[k + 3]) * r[k + 3], 0.f);
    return v;
}

// ---------------- utility kernels ----------------
__global__ void zero4_kernel(float4* p, long n4) {
    long i = (long)blockIdx.x * blockDim.x + threadIdx.x;
    if (i < n4) p[i] = make_float4(0.f, 0.f, 0.f, 0.f);
}
__global__ void zero_int(int* p, int n) {
    int i = blockIdx.x * blockDim.x + threadIdx.x;
    if (i < n) p[i] = 0;
}
__global__ void copy_kernel(float4* dst, const float4* src, long n4) {
    long i = (long)blockIdx.x * blockDim.x + threadIdx.x;
    if (i < n4) dst[i] = src[i];
}

// ---------------- bf16 split conversion ----------------
// A[M,K] fp32 (optional BN+relu) -> Y[Mpad][3K] bf16 as [hi | hi | lo]; rows >= Mreal zeroed
__global__ void split_a(const float* __restrict__ X, __nv_bfloat16* __restrict__ Y,
                        int Mreal, long total, int logK,
                        const float* __restrict__ mean, const float* __restrict__ rstd) {
    long i = (long)blockIdx.x * blockDim.x + threadIdx.x;
    if (i >= total) return;
    long m = i >> logK;
    int K = 1 << logK;
    int k = (int)(i & (K - 1));
    float v = 0.f;
    if (m < Mreal) {
        v = X[(m << logK) + k];
        if (mean) v = fmaxf((v - mean[k]) * rstd[k], 0.f);
    }
    __nv_bfloat16 h = __float2bfloat16(v);
    __nv_bfloat16 l = __float2bfloat16(v - __bfloat162float(h));
    __nv_bfloat16* yr = Y + m * 3 * K;
    yr[k] = h;
    yr[K + k] = h;
    yr[2 * K + k] = l;
}
// W[z][K][N] fp32 -> Y[z][N][3K] bf16 transposed split as [hi | lo | hi]
__global__ void split_b(const float* __restrict__ W, __nv_bfloat16* __restrict__ Y,
                        int logK, int N) {
    int z = blockIdx.y;
    int K = 1 << logK;
    long total = (long)N << logK;
    long i = (long)blockIdx.x * blockDim.x + threadIdx.x;
    if (i >= total) return;
    int n = (int)(i >> logK);
    int k = (int)(i & (K - 1));
    float v = W[((long)z * K + k) * N + n];
    __nv_bfloat16 h = __float2bfloat16(v);
    __nv_bfloat16 l = __float2bfloat16(v - __bfloat162float(h));
    __nv_bfloat16* yr = Y + ((long)z * N + n) * 3 * K;
    yr[k] = h;
    yr[K + k] = l;
    yr[2 * K + k] = h;
}

// ---------------- warp-MMA bf16 GEMM: C[M,ldc] (+)= A[Mpad,K3] @ B[N,K3]^T ----------------
// 128x128 tile, 8 warps (4x2), warp tile 32x64, BK=32. K3 % 32 == 0.
__global__ void __launch_bounds__(256)
bgemm(const __nv_bfloat16* __restrict__ A, const __nv_bfloat16* __restrict__ Bm,
      float* __restrict__ C, int M, int ldc, int K3, long sB, long sC, int addC) {
    __shared__ __align__(16) __nv_bfloat16 As[128][40];
    __shared__ __align__(16) __nv_bfloat16 Bs[128][40];
    int tid = threadIdx.x, wid = tid >> 5, lane = tid & 31;
    int row0 = blockIdx.y * 128, col0 = blockIdx.x * 128;
    const __nv_bfloat16* Az = A + (long)row0 * K3;
    const __nv_bfloat16* Bz = Bm + (long)blockIdx.z * sB + (long)col0 * K3;
    float* Cz = C + (long)blockIdx.z * sC;
    int wr = wid >> 1;           // 0..3
    int wc = wid & 1;            // 0..1
    int gid = lane >> 2, tig = lane & 3;
    int lrow = lane & 15;
    int lcol = (lane >> 4) << 3;  // 0 or 8

    float acc[2][8][4];
#pragma unroll
    for (int mt = 0; mt < 2; mt++)
#pragma unroll
        for (int nt = 0; nt < 8; nt++)
#pragma unroll
            for (int j = 0; j < 4; j++) acc[mt][nt][j] = 0.f;

    for (int k0 = 0; k0 < K3; k0 += 32) {
#pragma unroll
        for (int it = 0; it < 2; it++) {
            int idx = tid + it * 256;       // 0..511
            int r = idx >> 2;               // 0..127
            int cb = (idx & 3) << 3;        // 0,8,16,24
            *(uint4*)&As[r][cb] = *(const uint4*)(Az + (long)r * K3 + k0 + cb);
            *(uint4*)&Bs[r][cb] = *(const uint4*)(Bz + (long)r * K3 + k0 + cb);
        }
        __syncthreads();
#pragma unroll
        for (int ks = 0; ks < 2; ks++) {
            int kk = ks * 16;
            uint32_t afr[2][4];
#pragma unroll
            for (int mt = 0; mt < 2; mt++)
                ldmatrix_x4(afr[mt], smem_to_u32(&As[wr * 32 + mt * 16 + lrow][kk + lcol]));
            uint32_t bfr[4][4];
#pragma unroll
            for (int nb = 0; nb < 4; nb++)
                ldmatrix_x4(bfr[nb], smem_to_u32(&Bs[wc * 64 + nb * 16 + lrow][kk + lcol]));
#pragma unroll
            for (int mt = 0; mt < 2; mt++)
#pragma unroll
                for (int nb = 0; nb < 4; nb++) {
                    mma_bf16(acc[mt][2 * nb + 0], afr[mt], bfr[nb][0], bfr[nb][2]);
                    mma_bf16(acc[mt][2 * nb + 1], afr[mt], bfr[nb][1], bfr[nb][3]);
                }
        }
        __syncthreads();
    }
    // epilogue: d frags -> C. c0,c1 at (row gid, cols 2*tig,2*tig+1); c2,c3 at row gid+8.
#pragma unroll
    for (int mt = 0; mt < 2; mt++) {
        int r0 = row0 + wr * 32 + mt * 16 + gid;
#pragma unroll
        for (int nt = 0; nt < 8; nt++) {
            int c = col0 + wc * 64 + nt * 8 + 2 * tig;
            if (r0 < M) {
                float* p = Cz + (long)r0 * ldc + c;
                if (addC) { p[0] += acc[mt][nt][0]; p[1] += acc[mt][nt][1]; }
                else      { p[0]  = acc[mt][nt][0]; p[1]  = acc[mt][nt][1]; }
            }
            if (r0 + 8 < M) {
                float* p = Cz + (long)(r0 + 8) * ldc + c;
                if (addC) { p[0] += acc[mt][nt][2]; p[1] += acc[mt][nt][3]; }
                else      { p[0]  = acc[mt][nt][2]; p[1]  = acc[mt][nt][3]; }
            }
        }
    }
}

// ---------------- CSR build ----------------
__global__ void hist_mol_k(int* hist, const int* __restrict__ dst, int E) {
    int e = blockIdx.x * blockDim.x + threadIdx.x;
    if (e < E) atomicAdd(&hist[dst[e]], 1);
}
__global__ void hist_kg_k(int* hist, const int* __restrict__ dst, const int* __restrict__ et, int E) {
    int e = blockIdx.x * blockDim.x + threadIdx.x;
    if (e < E) atomicAdd(&hist[dst[e] * R_REL + et[e]], 1);
}
__global__ void scan_blk(const int* __restrict__ hist, int* __restrict__ base,
                         int* __restrict__ bsum, int n) {
    __shared__ int wsum[32];
    int b = blockIdx.x;
    int t = threadIdx.x, lane = t & 31, wid = t >> 5;
    int i0 = b * 4096 + t * 4;
    int v0 = (i0 < n) ? hist[i0] : 0;
    int v1 = (i0 + 1 < n) ? hist[i0 + 1] : 0;
    int v2 = (i0 + 2 < n) ? hist[i0 + 2] : 0;
    int v3 = (i0 + 3 < n) ? hist[i0 + 3] : 0;
    int s = v0 + v1 + v2 + v3;
    int sc = s;
#pragma unroll
    for (int o = 1; o < 32; o <<= 1) {
        int u = __shfl_up_sync(0xffffffffu, sc, o);
        if (lane >= o) sc += u;
    }
    if (lane == 31) wsum[wid] = sc;
    __syncthreads();
    if (wid == 0) {
        int w = wsum[lane];
        int wc = w;
#pragma unroll
        for (int o = 1; o < 32; o <<= 1) {
            int u = __shfl_up_sync(0xffffffffu, wc, o);
            if (lane >= o) wc += u;
        }
        wsum[lane] = wc - w;
    }
    __syncthreads();
    int excl = wsum[wid] + (sc - s);
    if (i0 < n) base[i0] = excl;
    excl += v0;
    if (i0 + 1 < n) base[i0 + 1] = excl;
    excl += v1;
    if (i0 + 2 < n) base[i0 + 2] = excl;
    excl += v2;
    if (i0 + 3 < n) base[i0 + 3] = excl;
    if (t == 1023) bsum[b] = wsum[31] + sc;
}
__global__ void scan_bsum(const int* __restrict__ bsum, int* __restrict__ boff, int nb) {
    int t = threadIdx.x;
    int v = (t < nb) ? bsum[t] : 0;
    int sc = v;
#pragma unroll
    for (int o = 1; o < 32; o <<= 1) {
        int u = __shfl_up_sync(0xffffffffu, sc, o);
        if (t >= o) sc += u;
    }
    if (t < nb) boff[t] = sc - v;
    if (t == 31) boff[nb] = sc;
}
__global__ void scan_add(int* __restrict__ base, int* __restrict__ off,
                         const int* __restrict__ boff, int n, int nb) {
    int i = blockIdx.x * blockDim.x + threadIdx.x;
    if (i < n) {
        int v = base[i] + boff[i >> 12];
        base[i] = v;
        off[i] = v;
    }
    if (i == 0) base[n] = boff[nb];
}
__global__ void reorder_mol(const int* __restrict__ src, const int* __restrict__ dst,
                            int* off, int* ssrc, int E) {
    int e = blockIdx.x * blockDim.x + threadIdx.x;
    if (e < E) {
        int p = atomicAdd(&off[dst[e]], 1);
        ssrc[p] = src[e];
    }
}
__global__ void reorder_kg(const int* __restrict__ src, const int* __restrict__ dst,
                           const int* __restrict__ et, int* off, int* ssrc, int E) {
    int e = blockIdx.x * blockDim.x + threadIdx.x;
    if (e < E) {
        int p = atomicAdd(&off[dst[e] * R_REL + et[e]], 1);
        ssrc[p] = src[e];
    }
}
__global__ void dinv_k(float* dinv, const int* __restrict__ hist, int n) {
    int i = blockIdx.x * blockDim.x + threadIdx.x;
    if (i < n) dinv[i] = rsqrtf((float)hist[i] + 1.0f);
}

// ---------------- GCN aggregation ----------------
__global__ void gcn_agg(const float* __restrict__ x, const int* __restrict__ ssrc,
                        const int* __restrict__ base, const float* __restrict__ dinv,
                        float* __restrict__ out, int logF,
                        const float* __restrict__ bmean, const float* __restrict__ brstd) {
    int F = 1 << logF;
    int t = threadIdx.x & (F - 1);
    int local = threadIdx.x >> logF;
    int d = blockIdx.x * (256 >> logF) + local;
    bool dobn = (bmean != nullptr);
    float m = 0.f, rs = 1.f;
    if (dobn) { m = bmean[t]; rs = brstd[t]; }
    int s0 = base[d], s1 = base[d + 1];
    float a0 = 0.f, a1 = 0.f;
    int p = s0;
    for (; p + 1 < s1; p += 2) {
        int sA = ssrc[p], sB = ssrc[p + 1];
        float vA = (x[((long)sA << logF) + t] - m) * rs;
        float vB = (x[((long)sB << logF) + t] - m) * rs;
        if (dobn) { vA = fmaxf(vA, 0.f); vB = fmaxf(vB, 0.f); }
        a0 += dinv[sA] * vA;
        a1 += dinv[sB] * vB;
    }
    if (p < s1) {
        int sA = ssrc[p];
        float vA = (x[((long)sA << logF) + t] - m) * rs;
        if (dobn) vA = fmaxf(vA, 0.f);
        a0 += dinv[sA] * vA;
    }
    float dd = dinv[d];
    float vs = (x[((long)d << logF) + t] - m) * rs;
    if (dobn) vs = fmaxf(vs, 0.f);
    out[((long)d << logF) + t] = dd * (a0 + a1) + dd * dd * vs;
}

// ---------------- RGCN aggregation ----------------
__global__ void rgcn_agg1(const float* __restrict__ x, const int* __restrict__ ssrc,
                          const int* __restrict__ base, float* __restrict__ AGG) {
    int d = blockIdx.x;
    int t = threadIdx.x;  // 256
#pragma unroll
    for (int r = 0; r < R_REL; r++) {
        int k = d * R_REL + r;
        int s0 = base[k], s1 = base[k + 1];
        float a0 = 0.f, a1 = 0.f;
        int p = s0;
        for (; p + 1 < s1; p += 2) {
            a0 += x[(long)ssrc[p] * 256 + t];
            a1 += x[(long)ssrc[p + 1] * 256 + t];
        }
        if (p < s1) a0 += x[(long)ssrc[p] * 256 + t];
        float nrm = (s1 > s0) ? 1.0f / (float)(s1 - s0) : 0.0f;
        AGG[(long)d * 2048 + r * 256 + t] = (a0 + a1) * nrm;
    }
}
__global__ void rgcn_agg2(const float* __restrict__ hr, const int* __restrict__ ssrc,
                          const int* __restrict__ base, float* __restrict__ xkg) {
    int d = blockIdx.x * 2 + (threadIdx.x >> 7);
    int t = threadIdx.x & 127;
    float tot = 0.f;
#pragma unroll
    for (int r = 0; r < R_REL; r++) {
        int k = d * R_REL + r;
        int s0 = base[k], s1 = base[k + 1];
        float a0 = 0.f, a1 = 0.f;
        int p = s0;
        const float* hp = hr + (long)r * N_KG * 128;
        for (; p + 1 < s1; p += 2) {
            a0 += hp[(long)ssrc[p] * 128 + t];
            a1 += hp[(long)ssrc[p + 1] * 128 + t];
        }
        if (p < s1) a0 += hp[(long)ssrc[p] * 128 + t];
        if (s1 > s0) tot += (a0 + a1) / (float)(s1 - s0);
    }
    if (d < N_KG) xkg[(long)d * 128 + t] += tot;
}

// ---------------- SGEMM (small GEMMs only) ----------------
__global__ __launch_bounds__(256, 2)
void sgemm128(const float* __restrict__ A, const float* __restrict__ B,
              float* __restrict__ C, int M, int N, int K, int lda,
              long sA, long sB, long sC, int accum,
              const float* __restrict__ abn_mean, const float* __restrict__ abn_rstd,
              int abn_zstride) {
    const int BM = 128, BN = 128, BK = 16;
    __shared__ float As[2][BK][BM + 4];
    __shared__ float Bs[2][BK][BN];
    const float* Ap = A + (long)blockIdx.z * sA;
    const float* Bp = B + (long)blockIdx.z * sB;
    float* Cp = C + (long)blockIdx.z * sC;
    const bool dobn = (abn_mean != nullptr);
    const int abn_off = abn_zstride * blockIdx.z;
    int tid = threadIdx.x;
    int row0 = blockIdx.y * BM, col0 = blockIdx.x * BN;
    int aRow = tid >> 2;
    int aCol = (tid & 3) << 2;
    int bRow = tid >> 5;
    int bCol = (tid & 31) << 2;
    int tm = (tid >> 4) << 3;
    int tn = (tid & 15) << 3;
    unsigned long long acc2[8][4];
#pragma unroll
    for (int i = 0; i < 8; i++)
#pragma unroll
        for (int j = 0; j < 4; j++) acc2[i][j] = 0ull;
    float4 ra[2], rb[2];
    int nk = K / BK;
    {
#pragma unroll
        for (int i = 0; i < 2; i++) {
            int gr = row0 + aRow + i * 64;
            float4 v = make_float4(0.f, 0.f, 0.f, 0.f);
            if (gr < M) v = *(const float4*)(Ap + (long)gr * lda + aCol);
            if (dobn) v = abn_apply4(v, abn_mean + abn_off, abn_rstd + abn_off, aCol);
            As[0][aCol + 0][aRow + i * 64] = v.x;
            As[0][aCol + 1][aRow + i * 64] = v.y;
            As[0][aCol + 2][aRow + i * 64] = v.z;
            As[0][aCol + 3][aRow + i * 64] = v.w;
        }
#pragma unroll
        for (int i = 0; i < 2; i++) {
            int gk = bRow + i * 8;
            int gc = col0 + bCol;
            float4 v = make_float4(0.f, 0.f, 0.f, 0.f);
            if (gc < N) v = *(const float4*)(Bp + (long)gk * N + gc);
            *(float4*)&Bs[0][bRow + i * 8][bCol] = v;
        }
    }
    __syncthreads();
    int cur = 0;
    for (int t = 0; t < nk; t++) {
        if (t + 1 < nk) {
            int k0 = (t + 1) * BK;
#pragma unroll
            for (int i = 0; i < 2; i++) {
                int gr = row0 + aRow + i * 64;
                ra[i] = make_float4(0.f, 0.f, 0.f, 0.f);
                if (gr < M) ra[i] = *(const float4*)(Ap + (long)gr * lda + k0 + aCol);
                if (dobn) ra[i] = abn_apply4(ra[i], abn_mean + abn_off, abn_rstd + abn_off, k0 + aCol);
            }
#pragma unroll
            for (int i = 0; i < 2; i++) {
                int gk = k0 + bRow + i * 8;
                int gc = col0 + bCol;
                rb[i] = make_float4(0.f, 0.f, 0.f, 0.f);
                if (gc < N) rb[i] = *(const float4*)(Bp + (long)gk * N + gc);
            }
        }
#pragma unroll
        for (int kk = 0; kk < BK; kk++) {
            union { float f[8]; float4 v[2]; } av;
            union { float f[8]; float4 v[2]; unsigned long long u[4]; } bv;
            av.v[0] = *(float4*)&As[cur][kk][tm];
            av.v[1] = *(float4*)&As[cur][kk][tm + 4];
            bv.v[0] = *(float4*)&Bs[cur][kk][tn];
            bv.v[1] = *(float4*)&Bs[cur][kk][tn + 4];
#pragma unroll
            for (int i = 0; i < 8; i++) {
                unsigned long long a2 = bcast2(av.f[i]);
#pragma unroll
                for (int jp = 0; jp < 4; jp++)
                    acc2[i][jp] = ffma2(a2, bv.u[jp], acc2[i][jp]);
            }
        }
        if (t + 1 < nk) {
            int nb = cur ^ 1;
#pragma unroll
            for (int i = 0; i < 2; i++) {
                As[nb][aCol + 0][aRow + i * 64] = ra[i].x;
                As[nb][aCol + 1][aRow + i * 64] = ra[i].y;
                As[nb][aCol + 2][aRow + i * 64] = ra[i].z;
                As[nb][aCol + 3][aRow + i * 64] = ra[i].w;
            }
#pragma unroll
            for (int i = 0; i < 2; i++)
                *(float4*)&Bs[nb][bRow + i * 8][bCol] = rb[i];
            __syncthreads();
            cur = nb;
        }
    }
    bool fullN = (col0 + BN <= N);
#pragma unroll
    for (int i = 0; i < 8; i++) {
        int gr = row0 + tm + i;
        if (gr >= M) break;
        float* accf = (float*)acc2[i];
        float* crow = Cp + (long)gr * N;
        if (fullN) {
            *(float4*)&crow[col0 + tn] = *(float4*)&accf[0];
            *(float4*)&crow[col0 + tn + 4] = *(float4*)&accf[4];
        } else {
#pragma unroll
            for (int j = 0; j < 8; j++) {
                int gc = col0 + tn + j;
                if (gc < N) crow[gc] = accf[j];
            }
        }
    }
}

// ---------------- BatchNorm stats ----------------
__global__ void bn_partial(const float* __restrict__ X, int M, int F,
                           float* __restrict__ colsum, float* __restrict__ colsq) {
    float s0 = 0.f, s1 = 0.f, q0 = 0.f, q1 = 0.f;
    int f0 = threadIdx.x, f1 = threadIdx.x + 256;
    for (int r = blockIdx.x; r < M; r += gridDim.x) {
        const float* row = X + (long)r * F;
        if (f0 < F) { float v = row[f0]; s0 += v; q0 += v * v; }
        if (f1 < F) { float v = row[f1]; s1 += v; q1 += v * v; }
    }
    if (f0 < F) { atomicAdd(&colsum[f0], s0); atomicAdd(&colsq[f0], q0); }
    if (f1 < F) { atomicAdd(&colsum[f1], s1); atomicAdd(&colsq[f1], q1); }
}
__global__ void bn_finalize(int M, int F, const float* __restrict__ colsum,
                            const float* __restrict__ colsq,
                            float* __restrict__ mean, float* __restrict__ rstd) {
    int f = blockIdx.x * blockDim.x + threadIdx.x;
    if (f < F) {
        float m = colsum[f] / (float)M;
        float v = colsq[f] / (float)M - m * m;
        mean[f] = m;
        rstd[f] = rsqrtf(fmaxf(v, 0.0f) + EPSV);
    }
}
__global__ void bn_pool(const float* __restrict__ X, const int* __restrict__ batch,
                        const float* __restrict__ mean, const float* __restrict__ rstd,
                        float* __restrict__ pool) {
    int g = blockIdx.x;
    int t = threadIdx.x;  // 256
    __shared__ int sh_lo, sh_hi;
    if (t == 0) {
        int lo = 0, hi = N_MOL;
        while (lo < hi) { int m = (lo + hi) >> 1; if (batch[m] < g) lo = m + 1; else hi = m; }
        sh_lo = lo;
        int lo2 = lo, hi2 = N_MOL;
        while (lo2 < hi2) { int m = (lo2 + hi2) >> 1; if (batch[m] <= g) lo2 = m + 1; else hi2 = m; }
        sh_hi = lo2;
    }
    __syncthreads();
    int lo = sh_lo, hi = sh_hi;
    float m = mean[t], rs = rstd[t];
    float acc = 0.f;
    for (int i = lo; i < hi; i++) {
        float v = (X[(long)i * 256 + t] - m) * rs;
        acc += fmaxf(v, 0.f);
    }
    float c = (float)(hi - lo);
    pool[(long)g * 256 + t] = acc / fmaxf(c, 1.0f);
}

// ---------------- attention fusion ----------------
__global__ void att_kernel(const float* __restrict__ pool,
                           const float* __restrict__ fp,
                           const float* __restrict__ fmean, const float* __restrict__ frstd,
                           const float* __restrict__ w1, const float* __restrict__ b1,
                           const float* __restrict__ w2, float* __restrict__ xkg,
                           float* __restrict__ beta_out) {
    int n = blockIdx.x;
    int tid = threadIdx.x;  // 128
    __shared__ float z0[256], z1[256];
    __shared__ float red0[4], red1[4];
    __shared__ float bsh[2];
    for (int i = tid; i < 256; i += 128) {
        z0[i] = pool[(long)n * 256 + i];
        z1[i] = fmaxf((fp[(long)n * 256 + i] - fmean[i]) * frstd[i], 0.f);
    }
    __syncthreads();
    float s0 = 0.f, s1 = 0.f;
#pragma unroll 4
    for (int d = 0; d < 256; d++) {
        float w = w1[d * 128 + tid];
        s0 += z0[d] * w;
        s1 += z1[d] * w;
    }
    float bb = b1[tid], ww = w2[tid];
    float t0 = tanhf(s0 + bb) * ww;
    float t1 = tanhf(s1 + bb) * ww;
#pragma unroll
    for (int o = 16; o > 0; o >>= 1) {
        t0 += __shfl_down_sync(0xffffffffu, t0, o);
        t1 += __shfl_down_sync(0xffffffffu, t1, o);
    }
    int wid = tid >> 5, lid = tid & 31;
    if (lid == 0) { red0[wid] = t0; red1[wid] = t1; }
    __syncthreads();
    if (tid == 0) {
        float a0 = red0[0] + red0[1] + red0[2] + red0[3];
        float a1 = red1[0] + red1[1] + red1[2] + red1[3];
        float m = fmaxf(a0, a1);
        float e0 = expf(a0 - m), e1 = expf(a1 - m);
        float inv = 1.0f / (e0 + e1);
        bsh[0] = e0 * inv; bsh[1] = e1 * inv;
        beta_out[2 * n] = e0 * inv;
        beta_out[2 * n + 1] = e1 * inv;
    }
    __syncthreads();
    float b0v = bsh[0], b1v = bsh[1];
    for (int i = tid; i < 256; i += 128)
        xkg[(long)n * 256 + i] = b0v * z0[i] + b1v * z1[i];
}

// ---------------- final head ----------------
__global__ void lin2_k(const float* __restrict__ x,
                       const float* __restrict__ mean, const float* __restrict__ rstd,
                       const float* __restrict__ w, const float* __restrict__ b,
                       float* __restrict__ out) {
    int row = blockIdx.x * blockDim.x + threadIdx.x;
    if (row >= N_KG) return;
    float l0 = b[0], l1 = b[1];
    const float* xr = x + (long)row * 64;
#pragma unroll
    for (int d = 0; d < 64; d++) {
        float v = fmaxf((xr[d] - mean[d]) * rstd[d], 0.f);
        l0 += v * w[2 * d];
        l1 += v * w[2 * d + 1];
    }
    float m = fmaxf(l0, l1);
    float lse = m + logf(expf(l0 - m) + expf(l1 - m));
    out[2 * row] = l0 - lse;
    out[2 * row + 1] = l1 - lse;
}

// ---------------- host driver ----------------
static inline int cdiv(long a, long b) { return (int)((a + b - 1) / b); }

static void gemm(const float* A, const float* B, float* C, int M, int N, int K, int lda,
                 long sA = 0, long sB = 0, long sC = 0, int z = 1, int accum = 0,
                 const float* abn_mean = nullptr, const float* abn_rstd = nullptr,
                 int abn_zstride = 0) {
    dim3 grid(cdiv(N, 128), cdiv(M, 128), z);
    sgemm128<<<grid, 256>>>(A, B, C, M, N, K, lda, sA, sB, sC, accum,
                            abn_mean, abn_rstd, abn_zstride);
}

extern "C" void kernel_launch(void* const* d_in, const int* in_sizes, int n_in,
                              void* d_out, int out_size) {
    const float* fp_data = (const float*)d_in[0];
    const float* mol_x   = (const float*)d_in[1];
    const int*   mol_batch = (const int*)d_in[2];
    const int*   mol_ei  = (const int*)d_in[3];
    const int*   kg_ei   = (const int*)d_in[4];
    const int*   kg_et   = (const int*)d_in[5];
    const float* fp_w1   = (const float*)d_in[6];
    const float* fp_w2   = (const float*)d_in[8];
    const float* gcn_w1  = (const float*)d_in[10];
    const float* gcn_w2  = (const float*)d_in[12];
    const float* att_w1  = (const float*)d_in[14];
    const float* att_b1  = (const float*)d_in[15];
    const float* att_w2  = (const float*)d_in[16];
    const float* gene_emb = (const float*)d_in[17];
    const float* rg_w1   = (const float*)d_in[18];
    const float* rg_root1 = (const float*)d_in[19];
    const float* rg_w2   = (const float*)d_in[21];
    const float* rg_root2 = (const float*)d_in[22];
    const float* lin1_w  = (const float*)d_in[24];
    const float* lin2_w  = (const float*)d_in[26];
    const float* lin2_b  = (const float*)d_in[27];
    float* out = (float*)d_out;

    float *h1, *fpb, *bufA, *bufB, *bufC, *dinv, *pool, *xkg, *hr, *agg, *x3, *stats;
    __nv_bfloat16 *asp, *bsp;
    int *hist_mol, *base_mol, *off_mol, *ssrc_mol, *hist_kg, *base_kg, *off_kg, *ssrc_kg;
    int *bsum, *boff;
    cudaGetSymbolAddress((void**)&h1, g_h1);
    cudaGetSymbolAddress((void**)&fpb, g_fp);
    cudaGetSymbolAddress((void**)&bufA, g_bufA);
    cudaGetSymbolAddress((void**)&bufB, g_bufB);
    cudaGetSymbolAddress((void**)&bufC, g_bufC);
    cudaGetSymbolAddress((void**)&dinv, g_dinv);
    cudaGetSymbolAddress((void**)&pool, g_pool);
    cudaGetSymbolAddress((void**)&xkg, g_xkg);
    cudaGetSymbolAddress((void**)&hr, g_hr);
    cudaGetSymbolAddress((void**)&agg, g_agg);
    cudaGetSymbolAddress((void**)&x3, g_x3);
    cudaGetSymbolAddress((void**)&stats, g_stats);
    cudaGetSymbolAddress((void**)&asp, g_asplit);
    cudaGetSymbolAddress((void**)&bsp, g_bsplit);
    cudaGetSymbolAddress((void**)&hist_mol, g_hist_mol);
    cudaGetSymbolAddress((void**)&base_mol, g_base_mol);
    cudaGetSymbolAddress((void**)&off_mol, g_off_mol);
    cudaGetSymbolAddress((void**)&ssrc_mol, g_ssrc_mol);
    cudaGetSymbolAddress((void**)&hist_kg, g_hist_kg);
    cudaGetSymbolAddress((void**)&base_kg, g_base_kg);
    cudaGetSymbolAddress((void**)&off_kg, g_off_kg);
    cudaGetSymbolAddress((void**)&ssrc_kg, g_ssrc_kg);
    cudaGetSymbolAddress((void**)&bsum, g_bsum);
    cudaGetSymbolAddress((void**)&boff, g_boff);

    float* S0 = stats;
    float* S1 = stats + 2048;
    float* S2 = stats + 4096;
    float* S3 = stats + 6144;
    float* S4 = stats + 8192;
    float* S5 = stats + 10240;
    float* S6 = stats + 12288;
#define MEAN(S) ((S) + 1024)
#define RSTD(S) ((S) + 1536)

    const int* msrc = mol_ei;
    const int* mdst = mol_ei + E_MOL_C;
    const int* ksrc = kg_ei;
    const int* kdst = kg_ei + E_KG_C;

    zero4_kernel<<<cdiv(7 * 2048 / 4, 256), 256>>>((float4*)stats, 7 * 2048 / 4);

    // ---- CSR build ----
    const int NB_MOL = (N_MOL + 4095) / 4096;
    const int NB_KG = (NKEY_KG + 4095) / 4096;
    zero_int<<<cdiv(N_MOL, 256), 256>>>(hist_mol, N_MOL);
    hist_mol_k<<<cdiv(E_MOL_C, 256), 256>>>(hist_mol, mdst, E_MOL_C);
    scan_blk<<<NB_MOL, 1024>>>(hist_mol, base_mol, bsum, N_MOL);
    scan_bsum<<<1, 32>>>(bsum, boff, NB_MOL);
    scan_add<<<cdiv(N_MOL, 1024), 1024>>>(base_mol, off_mol, boff, N_MOL, NB_MOL);
    dinv_k<<<cdiv(N_MOL, 256), 256>>>(dinv, hist_mol, N_MOL);
    reorder_mol<<<cdiv(E_MOL_C, 256), 256>>>(msrc, mdst, off_mol, ssrc_mol, E_MOL_C);

    zero_int<<<cdiv(NKEY_KG, 256), 256>>>(hist_kg, NKEY_KG);
    hist_kg_k<<<cdiv(E_KG_C, 256), 256>>>(hist_kg, kdst, kg_et, E_KG_C);
    scan_blk<<<NB_KG, 1024>>>(hist_kg, base_kg, bsum, NKEY_KG);
    scan_bsum<<<1, 32>>>(bsum, boff, NB_KG);
    scan_add<<<cdiv(NKEY_KG, 1024), 1024>>>(base_kg, off_kg, boff, NKEY_KG, NB_KG);
    reorder_kg<<<cdiv(E_KG_C, 256), 256>>>(ksrc, kdst, kg_et, off_kg, ssrc_kg, E_KG_C);

    // ---- fp1: h1 = fp_data @ fp_w1  (warp-MMA, split bf16) ----
    split_a<<<cdiv((long)N_DRUGS * MLP_IN, 256), 256>>>(fp_data, asp, N_DRUGS,
                                                        (long)N_DRUGS * MLP_IN, 10, nullptr, nullptr);
    split_b<<<dim3(cdiv((long)MLP_H * MLP_IN, 256), 1), 256>>>(fp_w1, bsp, 10, MLP_H);
    bgemm<<<dim3(MLP_H / 128, N_DRUGS / 128), 256>>>(asp, bsp, h1, N_DRUGS, MLP_H, 3 * MLP_IN, 0, 0, 0);
    bn_partial<<<1184, 256>>>(h1, N_DRUGS, MLP_H, S0, S0 + 512);
    bn_finalize<<<cdiv(MLP_H, 128), 128>>>(N_DRUGS, MLP_H, S0, S0 + 512, MEAN(S0), RSTD(S0));

    // ---- fp2: fpb = bn_relu(h1) @ fp_w2 ----
    split_a<<<cdiv((long)N_DRUGS * MLP_H, 256), 256>>>(h1, asp, N_DRUGS,
                                                       (long)N_DRUGS * MLP_H, 9, MEAN(S0), RSTD(S0));
    split_b<<<dim3(cdiv((long)DFEAT * MLP_H, 256), 1), 256>>>(fp_w2, bsp, 9, DFEAT);
    bgemm<<<dim3(DFEAT / 128, N_DRUGS / 128), 256>>>(asp, bsp, fpb, N_DRUGS, DFEAT, 3 * MLP_H, 0, 0, 0);
    bn_partial<<<1184, 256>>>(fpb, N_DRUGS, DFEAT, S1, S1 + 512);
    bn_finalize<<<cdiv(DFEAT, 128), 128>>>(N_DRUGS, DFEAT, S1, S1 + 512, MEAN(S1), RSTD(S1));

    // ---- conv1: bufB = agg(mol_x) @ gcn_w1 ----
    gcn_agg<<<N_MOL / 4, 256>>>(mol_x, ssrc_mol, base_mol, dinv, bufA, 6, nullptr, nullptr);
    split_a<<<cdiv((long)N_MOL * GCN_IN, 256), 256>>>(bufA, asp, N_MOL,
                                                      (long)N_MOL * GCN_IN, 6, nullptr, nullptr);
    split_b<<<dim3(cdiv((long)GCN_H * GCN_IN, 256), 1), 256>>>(gcn_w1, bsp, 6, GCN_H);
    bgemm<<<dim3(1, N_MOL / 128), 256>>>(asp, bsp, bufB, N_MOL, GCN_H, 3 * GCN_IN, 0, 0, 0);
    bn_partial<<<1184, 256>>>(bufB, N_MOL, GCN_H, S2, S2 + 512);
    bn_finalize<<<cdiv(GCN_H, 128), 128>>>(N_MOL, GCN_H, S2, S2 + 512, MEAN(S2), RSTD(S2));

    // ---- conv2: bufA = agg(bn_relu(bufB)) @ gcn_w2 ----
    gcn_agg<<<N_MOL / 2, 256>>>(bufB, ssrc_mol, base_mol, dinv, bufC, 7, MEAN(S2), RSTD(S2));
    split_a<<<cdiv((long)N_MOL * GCN_H, 256), 256>>>(bufC, asp, N_MOL,
                                                     (long)N_MOL * GCN_H, 7, nullptr, nullptr);
    split_b<<<dim3(cdiv((long)DFEAT * GCN_H, 256), 1), 256>>>(gcn_w2, bsp, 7, DFEAT);
    bgemm<<<dim3(DFEAT / 128, N_MOL / 128), 256>>>(asp, bsp, bufA, N_MOL, DFEAT, 3 * GCN_H, 0, 0, 0);
    bn_partial<<<1184, 256>>>(bufA, N_MOL, DFEAT, S3, S3 + 512);
    bn_finalize<<<cdiv(DFEAT, 128), 128>>>(N_MOL, DFEAT, S3, S3 + 512, MEAN(S3), RSTD(S3));
    bn_pool<<<N_DRUGS, 256>>>(bufA, mol_batch, MEAN(S3), RSTD(S3), pool);

    // ---- attention fusion ----
    att_kernel<<<N_DRUGS, 128>>>(pool, fpb, MEAN(S1), RSTD(S1),
                                 att_w1, att_b1, att_w2, xkg, out + N_KG * 2);
    copy_kernel<<<cdiv((long)N_GENE * DFEAT / 4, 256), 256>>>(
        (float4*)(xkg + (long)N_DRUGS * DFEAT), (const float4*)gene_emb, (long)N_GENE * DFEAT / 4);

    // ---- RGCN layer 1: agg = x@root1 (sgemm) + AGG@W1stack (warp-MMA, addC) ----
    rgcn_agg1<<<N_KG, 256>>>(xkg, ssrc_kg, base_kg, hr);
    gemm(xkg, rg_root1, agg, N_KG, DIM1, DFEAT, DFEAT);
    split_a<<<cdiv((long)N_KG_PAD * 2048, 256), 256>>>(hr, asp, N_KG,
                                                       (long)N_KG_PAD * 2048, 11, nullptr, nullptr);
    split_b<<<dim3(cdiv((long)DIM1 * 2048, 256), 1), 256>>>(rg_w1, bsp, 11, DIM1);
    bgemm<<<dim3(DIM1 / 128, N_KG_PAD / 128), 256>>>(asp, bsp, agg, N_KG, DIM1, 3 * 2048, 0, 0, 1);
    bn_partial<<<1184, 256>>>(agg, N_KG, DIM1, S4, S4 + 512);
    bn_finalize<<<cdiv(DIM1, 128), 128>>>(N_KG, DIM1, S4, S4 + 512, MEAN(S4), RSTD(S4));

    // ---- RGCN layer 2: hr[r] = bn_relu(agg) @ w2[r] (warp-MMA batched) ----
    split_a<<<cdiv((long)N_KG_PAD * DIM1, 256), 256>>>(agg, asp, N_KG,
                                                       (long)N_KG_PAD * DIM1, 8, MEAN(S4), RSTD(S4));
    split_b<<<dim3(cdiv((long)DIM2 * DIM1, 256), R_REL), 256>>>(rg_w2, bsp, 8, DIM2);
    bgemm<<<dim3(1, N_KG_PAD / 128, R_REL), 256>>>(asp, bsp, hr, N_KG, DIM2, 3 * DIM1,
                                                   (long)DIM2 * 3 * DIM1, (long)N_KG * DIM2, 0);
    gemm(agg, rg_root2, xkg, N_KG, DIM2, DIM1, DIM1, 0, 0, 0, 1, 0, MEAN(S4), RSTD(S4), 0);
    rgcn_agg2<<<cdiv(N_KG, 2), 256>>>(hr, ssrc_kg, base_kg, xkg);
    bn_partial<<<1184, 256>>>(xkg, N_KG, DIM2, S5, S5 + 512);
    bn_finalize<<<cdiv(DIM2, 128), 128>>>(N_KG, DIM2, S5, S5 + 512, MEAN(S5), RSTD(S5));

    // ---- lin1 (sgemm, BN-A fused) ----
    gemm(xkg, lin1_w, x3, N_KG, DIM3, DIM2, DIM2, 0, 0, 0, 1, 0, MEAN(S5), RSTD(S5), 0);
    bn_partial<<<1184, 256>>>(x3, N_KG, DIM3, S6, S6 + 512);
    bn_finalize<<<1, 128>>>(N_KG, DIM3, S6, S6 + 512, MEAN(S6), RSTD(S6));

    // ---- lin2 + log_softmax ----
    lin2_k<<<cdiv(N_KG, 128), 128>>>(x3, MEAN(S6), RSTD(S6), lin2_w, lin2_b, out);
}

// round 11
// speedup vs baseline: 1.2115x; 1.2115x over previous
#include <cuda_runtime.h>
#include <cuda_bf16.h>
#include <cstdint>
#include <math.h>

#define N_DRUGS 4096
#define N_GENE  5414
#define N_KG    9510
#define N_MOL   131072
#define E_MOL_C 524288
#define E_KG_C  524288
#define R_REL   8
#define MLP_IN  1024
#define MLP_H   512
#define DFEAT   256
#define GCN_IN  64
#define GCN_H   128
#define DIM1    256
#define DIM2    128
#define DIM3    64
#define EPSV    1e-5f
#define NKEY_KG (N_KG * R_REL)

// ---------------- scratch ----------------
__device__ __align__(16) float g_h1[N_DRUGS * MLP_H];
__device__ __align__(16) float g_fp[N_DRUGS * DFEAT];
__device__ __align__(16) float g_bufA[(long)N_MOL * DFEAT];
__device__ __align__(16) float g_bufB[(long)N_MOL * DFEAT];
__device__ __align__(16) float g_bufC[(long)N_MOL * DFEAT];
__device__ __align__(16) float g_dinv[N_MOL];
__device__ __align__(16) float g_pool[N_DRUGS * DFEAT];
__device__ __align__(16) float g_xkg[N_KG * DFEAT];
__device__ __align__(16) float g_hr[(long)R_REL * N_KG * DFEAT];   // also AGG [N_KG, 2048]
__device__ __align__(16) float g_agg[N_KG * DFEAT];
__device__ __align__(16) float g_x3[N_KG * DIM3];
__device__ __align__(16) float g_stats[7 * 2048];
// bf16 split weight planes: per z, [hi N*K | lo N*K]
__device__ __align__(16) __nv_bfloat16 g_bsplit[2 * 1024 * 1024 + 65536];
// CSR scratch
__device__ int g_hist_mol[N_MOL];
__device__ int g_base_mol[N_MOL + 1];
__device__ int g_off_mol[N_MOL];
__device__ int g_ssrc_mol[E_MOL_C];
__device__ int g_hist_kg[NKEY_KG];
__device__ int g_base_kg[NKEY_KG + 1];
__device__ int g_off_kg[NKEY_KG];
__device__ int g_ssrc_kg[E_KG_C];
__device__ int g_bsum[64];
__device__ int g_boff[65];

// ---------------- warp-MMA helpers (baseline PTX, sm_80+) ----------------
__device__ __forceinline__ uint32_t smem_to_u32(const void* p) {
    uint32_t a;
    asm("{ .reg .u64 t; cvta.to.shared.u64 t, %1; cvt.u32.u64 %0, t; }" : "=r"(a) : "l"(p));
    return a;
}
__device__ __forceinline__ void ldmatrix_x4(uint32_t* r, uint32_t addr) {
    asm volatile("ldmatrix.sync.aligned.m8n8.x4.shared.b16 {%0,%1,%2,%3}, [%4];"
                 : "=r"(r[0]), "=r"(r[1]), "=r"(r[2]), "=r"(r[3]) : "r"(addr));
}
__device__ __forceinline__ void mma_bf16(float* d, const uint32_t* a, uint32_t b0, uint32_t b1) {
    asm volatile("mma.sync.aligned.m16n8k16.row.col.f32.bf16.bf16.f32 "
                 "{%0,%1,%2,%3}, {%4,%5,%6,%7}, {%8,%9}, {%0,%1,%2,%3};"
                 : "+f"(d[0]), "+f"(d[1]), "+f"(d[2]), "+f"(d[3])
                 : "r"(a[0]), "r"(a[1]), "r"(a[2]), "r"(a[3]), "r"(b0), "r"(b1));
}

// ---------------- misc helpers ----------------
__device__ __forceinline__ float4 abn_apply4(float4 v, const float* m, const float* r, int k) {
    v.x = fmaxf((v.x - m[k + 0]) * r[k + 0], 0.f);
    v.y = fmaxf((v.y - m[k + 1]) * r[k + 1], 0.f);
    v.z = fmaxf((v.z - m[k + 2]) * r[k + 2], 0.f);
    v.w = fmaxf((v.w - m[k + 3]) * r[k + 3], 0.f);
    return v;
}

// ---------------- utility kernels ----------------
__global__ void zero4_kernel(float4* p, long n4) {
    long i = (long)blockIdx.x * blockDim.x + threadIdx.x;
    if (i < n4) p[i] = make_float4(0.f, 0.f, 0.f, 0.f);
}
__global__ void zero_int(int* p, int n) {
    int i = blockIdx.x * blockDim.x + threadIdx.x;
    if (i < n) p[i] = 0;
}
__global__ void copy_kernel(float4* dst, const float4* src, long n4) {
    long i = (long)blockIdx.x * blockDim.x + threadIdx.x;
    if (i < n4) dst[i] = src[i];
}

// ---------------- bf16 weight split: W[z][K][N] fp32 -> per z planes [hi NxK | lo NxK] ----------------
__global__ void split_b2(const float* __restrict__ W, __nv_bfloat16* __restrict__ Y,
                         int logK, int N) {
    int z = blockIdx.y;
    int K = 1 << logK;
    long total = (long)N << logK;
    long i = (long)blockIdx.x * blockDim.x + threadIdx.x;
    if (i >= total) return;
    int n = (int)(i >> logK);
    int k = (int)(i & (K - 1));
    float v = W[((long)z * K + k) * N + n];
    __nv_bfloat16 h = __float2bfloat16(v);
    __nv_bfloat16 l = __float2bfloat16(v - __bfloat162float(h));
    __nv_bfloat16* base = Y + (long)z * 2 * total;
    base[(long)n * K + k] = h;
    base[total + (long)n * K + k] = l;
}

// ---------------- HMMA split-fp32 GEMM: C[M,ldc] (+)= A[M,K]fp32 @ Bsp[N,K]^T ----------------
// A converted to bf16 hi/lo in-kernel; 3-term product AhBh + AhBl + AlBh (fp32 accum).
// Optional BN+relu fused on A (abn_mean/rstd over K). Tile 128x128, 8 warps, BK=32.
__global__ void __launch_bounds__(256)
bgemm2(const float* __restrict__ A, const __nv_bfloat16* __restrict__ Bsp,
       float* __restrict__ C, int M, int N, int ldc, int K,
       long sA, long sC, int addC,
       const float* __restrict__ abn_mean, const float* __restrict__ abn_rstd) {
    __shared__ __align__(16) __nv_bfloat16 Ah[128][40];
    __shared__ __align__(16) __nv_bfloat16 Al[128][40];
    __shared__ __align__(16) __nv_bfloat16 Bh[128][40];
    __shared__ __align__(16) __nv_bfloat16 Bl[128][40];
    int tid = threadIdx.x, wid = tid >> 5, lane = tid & 31;
    int row0 = blockIdx.y * 128, col0 = blockIdx.x * 128;
    const float* Az = A + (long)blockIdx.z * sA;
    long planeN = (long)N * K;
    const __nv_bfloat16* Bz = Bsp + (long)blockIdx.z * 2 * planeN;
    float* Cz = C + (long)blockIdx.z * sC;
    const bool dobn = (abn_mean != nullptr);
    int wr = wid >> 1;            // 0..3
    int wc = wid & 1;             // 0..1
    int gid = lane >> 2, tig = lane & 3;
    int lrow = lane & 15;
    int lcol = (lane >> 4) << 3;  // 0 or 8

    float acc[2][8][4];
#pragma unroll
    for (int mt = 0; mt < 2; mt++)
#pragma unroll
        for (int nt = 0; nt < 8; nt++)
#pragma unroll
            for (int j = 0; j < 4; j++) acc[mt][nt][j] = 0.f;

    for (int k0 = 0; k0 < K; k0 += 32) {
        // stage A: fp32 -> (hi,lo) bf16
#pragma unroll
        for (int it = 0; it < 4; it++) {
            int idx = tid + it * 256;       // 0..1023
            int r = idx >> 3;               // 0..127
            int c = (idx & 7) << 2;         // 0..28
            float4 v = make_float4(0.f, 0.f, 0.f, 0.f);
            if (row0 + r < M) v = *(const float4*)(Az + (long)(row0 + r) * K + k0 + c);
            if (dobn) v = abn_apply4(v, abn_mean, abn_rstd, k0 + c);
            float vf[4] = {v.x, v.y, v.z, v.w};
#pragma unroll
            for (int j = 0; j < 4; j++) {
                __nv_bfloat16 h = __float2bfloat16(vf[j]);
                Ah[r][c + j] = h;
                Al[r][c + j] = __float2bfloat16(vf[j] - __bfloat162float(h));
            }
        }
        // stage B planes
#pragma unroll
        for (int it = 0; it < 2; it++) {
            int idx = tid + it * 256;       // 0..511
            int r = idx >> 2;               // 0..127
            int cb = (idx & 3) << 3;        // 0,8,16,24
            int n = col0 + r;
            uint4 vh = make_uint4(0, 0, 0, 0), vl = make_uint4(0, 0, 0, 0);
            if (n < N) {
                vh = *(const uint4*)(Bz + (long)n * K + k0 + cb);
                vl = *(const uint4*)(Bz + planeN + (long)n * K + k0 + cb);
            }
            *(uint4*)&Bh[r][cb] = vh;
            *(uint4*)&Bl[r][cb] = vl;
        }
        __syncthreads();
#pragma unroll
        for (int ks = 0; ks < 2; ks++) {
            int kk = ks * 16;
            uint32_t ah[2][4], al[2][4];
#pragma unroll
            for (int mt = 0; mt < 2; mt++) {
                ldmatrix_x4(ah[mt], smem_to_u32(&Ah[wr * 32 + mt * 16 + lrow][kk + lcol]));
                ldmatrix_x4(al[mt], smem_to_u32(&Al[wr * 32 + mt * 16 + lrow][kk + lcol]));
            }
#pragma unroll
            for (int nb = 0; nb < 4; nb++) {
                uint32_t bh[4], bl[4];
                ldmatrix_x4(bh, smem_to_u32(&Bh[wc * 64 + nb * 16 + lrow][kk + lcol]));
                ldmatrix_x4(bl, smem_to_u32(&Bl[wc * 64 + nb * 16 + lrow][kk + lcol]));
#pragma unroll
                for (int mt = 0; mt < 2; mt++) {
                    float* a0 = acc[mt][2 * nb + 0];
                    float* a1 = acc[mt][2 * nb + 1];
                    mma_bf16(a0, ah[mt], bh[0], bh[2]);
                    mma_bf16(a1, ah[mt], bh[1], bh[3]);
                    mma_bf16(a0, ah[mt], bl[0], bl[2]);
                    mma_bf16(a1, ah[mt], bl[1], bl[3]);
                    mma_bf16(a0, al[mt], bh[0], bh[2]);
                    mma_bf16(a1, al[mt], bh[1], bh[3]);
                }
            }
        }
        __syncthreads();
    }
    // epilogue
#pragma unroll
    for (int mt = 0; mt < 2; mt++) {
        int r0 = row0 + wr * 32 + mt * 16 + gid;
#pragma unroll
        for (int nt = 0; nt < 8; nt++) {
            int c = col0 + wc * 64 + nt * 8 + 2 * tig;
            if (c < N) {
                if (r0 < M) {
                    float* p = Cz + (long)r0 * ldc + c;
                    if (addC) { p[0] += acc[mt][nt][0]; p[1] += acc[mt][nt][1]; }
                    else      { p[0]  = acc[mt][nt][0]; p[1]  = acc[mt][nt][1]; }
                }
                if (r0 + 8 < M) {
                    float* p = Cz + (long)(r0 + 8) * ldc + c;
                    if (addC) { p[0] += acc[mt][nt][2]; p[1] += acc[mt][nt][3]; }
                    else      { p[0]  = acc[mt][nt][2]; p[1]  = acc[mt][nt][3]; }
                }
            }
        }
    }
}

// ---------------- CSR build ----------------
__global__ void hist_mol_k(int* hist, const int* __restrict__ dst, int E) {
    int e = blockIdx.x * blockDim.x + threadIdx.x;
    if (e < E) atomicAdd(&hist[dst[e]], 1);
}
__global__ void hist_kg_k(int* hist, const int* __restrict__ dst, const int* __restrict__ et, int E) {
    int e = blockIdx.x * blockDim.x + threadIdx.x;
    if (e < E) atomicAdd(&hist[dst[e] * R_REL + et[e]], 1);
}
__global__ void scan_blk(const int* __restrict__ hist, int* __restrict__ base,
                         int* __restrict__ bsum, int n) {
    __shared__ int wsum[32];
    int b = blockIdx.x;
    int t = threadIdx.x, lane = t & 31, wid = t >> 5;
    int i0 = b * 4096 + t * 4;
    int v0 = (i0 < n) ? hist[i0] : 0;
    int v1 = (i0 + 1 < n) ? hist[i0 + 1] : 0;
    int v2 = (i0 + 2 < n) ? hist[i0 + 2] : 0;
    int v3 = (i0 + 3 < n) ? hist[i0 + 3] : 0;
    int s = v0 + v1 + v2 + v3;
    int sc = s;
#pragma unroll
    for (int o = 1; o < 32; o <<= 1) {
        int u = __shfl_up_sync(0xffffffffu, sc, o);
        if (lane >= o) sc += u;
    }
    if (lane == 31) wsum[wid] = sc;
    __syncthreads();
    if (wid == 0) {
        int w = wsum[lane];
        int wc = w;
#pragma unroll
        for (int o = 1; o < 32; o <<= 1) {
            int u = __shfl_up_sync(0xffffffffu, wc, o);
            if (lane >= o) wc += u;
        }
        wsum[lane] = wc - w;
    }
    __syncthreads();
    int excl = wsum[wid] + (sc - s);
    if (i0 < n) base[i0] = excl;
    excl += v0;
    if (i0 + 1 < n) base[i0 + 1] = excl;
    excl += v1;
    if (i0 + 2 < n) base[i0 + 2] = excl;
    excl += v2;
    if (i0 + 3 < n) base[i0 + 3] = excl;
    if (t == 1023) bsum[b] = wsum[31] + sc;
}
__global__ void scan_bsum(const int* __restrict__ bsum, int* __restrict__ boff, int nb) {
    int t = threadIdx.x;
    int v = (t < nb) ? bsum[t] : 0;
    int sc = v;
#pragma unroll
    for (int o = 1; o < 32; o <<= 1) {
        int u = __shfl_up_sync(0xffffffffu, sc, o);
        if (t >= o) sc += u;
    }
    if (t < nb) boff[t] = sc - v;
    if (t == 31) boff[nb] = sc;
}
__global__ void scan_add(int* __restrict__ base, int* __restrict__ off,
                         const int* __restrict__ boff, int n, int nb) {
    int i = blockIdx.x * blockDim.x + threadIdx.x;
    if (i < n) {
        int v = base[i] + boff[i >> 12];
        base[i] = v;
        off[i] = v;
    }
    if (i == 0) base[n] = boff[nb];
}
__global__ void reorder_mol(const int* __restrict__ src, const int* __restrict__ dst,
                            int* off, int* ssrc, int E) {
    int e = blockIdx.x * blockDim.x + threadIdx.x;
    if (e < E) {
        int p = atomicAdd(&off[dst[e]], 1);
        ssrc[p] = src[e];
    }
}
__global__ void reorder_kg(const int* __restrict__ src, const int* __restrict__ dst,
                           const int* __restrict__ et, int* off, int* ssrc, int E) {
    int e = blockIdx.x * blockDim.x + threadIdx.x;
    if (e < E) {
        int p = atomicAdd(&off[dst[e] * R_REL + et[e]], 1);
        ssrc[p] = src[e];
    }
}
__global__ void dinv_k(float* dinv, const int* __restrict__ hist, int n) {
    int i = blockIdx.x * blockDim.x + threadIdx.x;
    if (i < n) dinv[i] = rsqrtf((float)hist[i] + 1.0f);
}

// ---------------- GCN aggregation ----------------
__global__ void gcn_agg(const float* __restrict__ x, const int* __restrict__ ssrc,
                        const int* __restrict__ base, const float* __restrict__ dinv,
                        float* __restrict__ out, int logF,
                        const float* __restrict__ bmean, const float* __restrict__ brstd) {
    int F = 1 << logF;
    int t = threadIdx.x & (F - 1);
    int local = threadIdx.x >> logF;
    int d = blockIdx.x * (256 >> logF) + local;
    bool dobn = (bmean != nullptr);
    float m = 0.f, rs = 1.f;
    if (dobn) { m = bmean[t]; rs = brstd[t]; }
    int s0 = base[d], s1 = base[d + 1];
    float a0 = 0.f, a1 = 0.f;
    int p = s0;
    for (; p + 1 < s1; p += 2) {
        int sA = ssrc[p], sB = ssrc[p + 1];
        float vA = (x[((long)sA << logF) + t] - m) * rs;
        float vB = (x[((long)sB << logF) + t] - m) * rs;
        if (dobn) { vA = fmaxf(vA, 0.f); vB = fmaxf(vB, 0.f); }
        a0 += dinv[sA] * vA;
        a1 += dinv[sB] * vB;
    }
    if (p < s1) {
        int sA = ssrc[p];
        float vA = (x[((long)sA << logF) + t] - m) * rs;
        if (dobn) vA = fmaxf(vA, 0.f);
        a0 += dinv[sA] * vA;
    }
    float dd = dinv[d];
    float vs = (x[((long)d << logF) + t] - m) * rs;
    if (dobn) vs = fmaxf(vs, 0.f);
    out[((long)d << logF) + t] = dd * (a0 + a1) + dd * dd * vs;
}

// ---------------- RGCN aggregation ----------------
__global__ void rgcn_agg1(const float* __restrict__ x, const int* __restrict__ ssrc,
                          const int* __restrict__ base, float* __restrict__ AGG) {
    int d = blockIdx.x;
    int t = threadIdx.x;  // 256
#pragma unroll
    for (int r = 0; r < R_REL; r++) {
        int k = d * R_REL + r;
        int s0 = base[k], s1 = base[k + 1];
        float a0 = 0.f, a1 = 0.f;
        int p = s0;
        for (; p + 1 < s1; p += 2) {
            a0 += x[(long)ssrc[p] * 256 + t];
            a1 += x[(long)ssrc[p + 1] * 256 + t];
        }
        if (p < s1) a0 += x[(long)ssrc[p] * 256 + t];
        float nrm = (s1 > s0) ? 1.0f / (float)(s1 - s0) : 0.0f;
        AGG[(long)d * 2048 + r * 256 + t] = (a0 + a1) * nrm;
    }
}
__global__ void rgcn_agg2(const float* __restrict__ hr, const int* __restrict__ ssrc,
                          const int* __restrict__ base, float* __restrict__ xkg) {
    int d = blockIdx.x * 2 + (threadIdx.x >> 7);
    int t = threadIdx.x & 127;
    float tot = 0.f;
#pragma unroll
    for (int r = 0; r < R_REL; r++) {
        int k = d * R_REL + r;
        int s0 = base[k], s1 = base[k + 1];
        float a0 = 0.f, a1 = 0.f;
        int p = s0;
        const float* hp = hr + (long)r * N_KG * 128;
        for (; p + 1 < s1; p += 2) {
            a0 += hp[(long)ssrc[p] * 128 + t];
            a1 += hp[(long)ssrc[p + 1] * 128 + t];
        }
        if (p < s1) a0 += hp[(long)ssrc[p] * 128 + t];
        if (s1 > s0) tot += (a0 + a1) / (float)(s1 - s0);
    }
    if (d < N_KG) xkg[(long)d * 128 + t] += tot;
}

// ---------------- BatchNorm stats ----------------
__global__ void bn_partial(const float* __restrict__ X, int M, int F,
                           float* __restrict__ colsum, float* __restrict__ colsq) {
    float s0 = 0.f, s1 = 0.f, q0 = 0.f, q1 = 0.f;
    int f0 = threadIdx.x, f1 = threadIdx.x + 256;
    for (int r = blockIdx.x; r < M; r += gridDim.x) {
        const float* row = X + (long)r * F;
        if (f0 < F) { float v = row[f0]; s0 += v; q0 += v * v; }
        if (f1 < F) { float v = row[f1]; s1 += v; q1 += v * v; }
    }
    if (f0 < F) { atomicAdd(&colsum[f0], s0); atomicAdd(&colsq[f0], q0); }
    if (f1 < F) { atomicAdd(&colsum[f1], s1); atomicAdd(&colsq[f1], q1); }
}
__global__ void bn_finalize(int M, int F, const float* __restrict__ colsum,
                            const float* __restrict__ colsq,
                            float* __restrict__ mean, float* __restrict__ rstd) {
    int f = blockIdx.x * blockDim.x + threadIdx.x;
    if (f < F) {
        float m = colsum[f] / (float)M;
        float v = colsq[f] / (float)M - m * m;
        mean[f] = m;
        rstd[f] = rsqrtf(fmaxf(v, 0.0f) + EPSV);
    }
}
__global__ void bn_pool(const float* __restrict__ X, const int* __restrict__ batch,
                        const float* __restrict__ mean, const float* __restrict__ rstd,
                        float* __restrict__ pool) {
    int g = blockIdx.x;
    int t = threadIdx.x;  // 256
    __shared__ int sh_lo, sh_hi;
    if (t == 0) {
        int lo = 0, hi = N_MOL;
        while (lo < hi) { int m = (lo + hi) >> 1; if (batch[m] < g) lo = m + 1; else hi = m; }
        sh_lo = lo;
        int lo2 = lo, hi2 = N_MOL;
        while (lo2 < hi2) { int m = (lo2 + hi2) >> 1; if (batch[m] <= g) lo2 = m + 1; else hi2 = m; }
        sh_hi = lo2;
    }
    __syncthreads();
    int lo = sh_lo, hi = sh_hi;
    float m = mean[t], rs = rstd[t];
    float acc = 0.f;
    for (int i = lo; i < hi; i++) {
        float v = (X[(long)i * 256 + t] - m) * rs;
        acc += fmaxf(v, 0.f);
    }
    float c = (float)(hi - lo);
    pool[(long)g * 256 + t] = acc / fmaxf(c, 1.0f);
}

// ---------------- attention fusion ----------------
__global__ void att_kernel(const float* __restrict__ pool,
                           const float* __restrict__ fp,
                           const float* __restrict__ fmean, const float* __restrict__ frstd,
                           const float* __restrict__ w1, const float* __restrict__ b1,
                           const float* __restrict__ w2, float* __restrict__ xkg,
                           float* __restrict__ beta_out) {
    int n = blockIdx.x;
    int tid = threadIdx.x;  // 128
    __shared__ float z0[256], z1[256];
    __shared__ float red0[4], red1[4];
    __shared__ float bsh[2];
    for (int i = tid; i < 256; i += 128) {
        z0[i] = pool[(long)n * 256 + i];
        z1[i] = fmaxf((fp[(long)n * 256 + i] - fmean[i]) * frstd[i], 0.f);
    }
    __syncthreads();
    float s0 = 0.f, s1 = 0.f;
#pragma unroll 4
    for (int d = 0; d < 256; d++) {
        float w = w1[d * 128 + tid];
        s0 += z0[d] * w;
        s1 += z1[d] * w;
    }
    float bb = b1[tid], ww = w2[tid];
    float t0 = tanhf(s0 + bb) * ww;
    float t1 = tanhf(s1 + bb) * ww;
#pragma unroll
    for (int o = 16; o > 0; o >>= 1) {
        t0 += __shfl_down_sync(0xffffffffu, t0, o);
        t1 += __shfl_down_sync(0xffffffffu, t1, o);
    }
    int wid = tid >> 5, lid = tid & 31;
    if (lid == 0) { red0[wid] = t0; red1[wid] = t1; }
    __syncthreads();
    if (tid == 0) {
        float a0 = red0[0] + red0[1] + red0[2] + red0[3];
        float a1 = red1[0] + red1[1] + red1[2] + red1[3];
        float m = fmaxf(a0, a1);
        float e0 = expf(a0 - m), e1 = expf(a1 - m);
        float inv = 1.0f / (e0 + e1);
        bsh[0] = e0 * inv; bsh[1] = e1 * inv;
        beta_out[2 * n] = e0 * inv;
        beta_out[2 * n + 1] = e1 * inv;
    }
    __syncthreads();
    float b0v = bsh[0], b1v = bsh[1];
    for (int i = tid; i < 256; i += 128)
        xkg[(long)n * 256 + i] = b0v * z0[i] + b1v * z1[i];
}

// ---------------- final head ----------------
__global__ void lin2_k(const float* __restrict__ x,
                       const float* __restrict__ mean, const float* __restrict__ rstd,
                       const float* __restrict__ w, const float* __restrict__ b,
                       float* __restrict__ out) {
    int row = blockIdx.x * blockDim.x + threadIdx.x;
    if (row >= N_KG) return;
    float l0 = b[0], l1 = b[1];
    const float* xr = x + (long)row * 64;
#pragma unroll
    for (int d = 0; d < 64; d++) {
        float v = fmaxf((xr[d] - mean[d]) * rstd[d], 0.f);
        l0 += v * w[2 * d];
        l1 += v * w[2 * d + 1];
    }
    float m = fmaxf(l0, l1);
    float lse = m + logf(expf(l0 - m) + expf(l1 - m));
    out[2 * row] = l0 - lse;
    out[2 * row + 1] = l1 - lse;
}

// ---------------- host driver ----------------
static inline int cdiv(long a, long b) { return (int)((a + b - 1) / b); }

extern "C" void kernel_launch(void* const* d_in, const int* in_sizes, int n_in,
                              void* d_out, int out_size) {
    const float* fp_data = (const float*)d_in[0];
    const float* mol_x   = (const float*)d_in[1];
    const int*   mol_batch = (const int*)d_in[2];
    const int*   mol_ei  = (const int*)d_in[3];
    const int*   kg_ei   = (const int*)d_in[4];
    const int*   kg_et   = (const int*)d_in[5];
    const float* fp_w1   = (const float*)d_in[6];
    const float* fp_w2   = (const float*)d_in[8];
    const float* gcn_w1  = (const float*)d_in[10];
    const float* gcn_w2  = (const float*)d_in[12];
    const float* att_w1  = (const float*)d_in[14];
    const float* att_b1  = (const float*)d_in[15];
    const float* att_w2  = (const float*)d_in[16];
    const float* gene_emb = (const float*)d_in[17];
    const float* rg_w1   = (const float*)d_in[18];
    const float* rg_root1 = (const float*)d_in[19];
    const float* rg_w2   = (const float*)d_in[21];
    const float* rg_root2 = (const float*)d_in[22];
    const float* lin1_w  = (const float*)d_in[24];
    const float* lin2_w  = (const float*)d_in[26];
    const float* lin2_b  = (const float*)d_in[27];
    float* out = (float*)d_out;

    float *h1, *fpb, *bufA, *bufB, *bufC, *dinv, *pool, *xkg, *hr, *agg, *x3, *stats;
    __nv_bfloat16* bsp;
    int *hist_mol, *base_mol, *off_mol, *ssrc_mol, *hist_kg, *base_kg, *off_kg, *ssrc_kg;
    int *bsum, *boff;
    cudaGetSymbolAddress((void**)&h1, g_h1);
    cudaGetSymbolAddress((void**)&fpb, g_fp);
    cudaGetSymbolAddress((void**)&bufA, g_bufA);
    cudaGetSymbolAddress((void**)&bufB, g_bufB);
    cudaGetSymbolAddress((void**)&bufC, g_bufC);
    cudaGetSymbolAddress((void**)&dinv, g_dinv);
    cudaGetSymbolAddress((void**)&pool, g_pool);
    cudaGetSymbolAddress((void**)&xkg, g_xkg);
    cudaGetSymbolAddress((void**)&hr, g_hr);
    cudaGetSymbolAddress((void**)&agg, g_agg);
    cudaGetSymbolAddress((void**)&x3, g_x3);
    cudaGetSymbolAddress((void**)&stats, g_stats);
    cudaGetSymbolAddress((void**)&bsp, g_bsplit);
    cudaGetSymbolAddress((void**)&hist_mol, g_hist_mol);
    cudaGetSymbolAddress((void**)&base_mol, g_base_mol);
    cudaGetSymbolAddress((void**)&off_mol, g_off_mol);
    cudaGetSymbolAddress((void**)&ssrc_mol, g_ssrc_mol);
    cudaGetSymbolAddress((void**)&hist_kg, g_hist_kg);
    cudaGetSymbolAddress((void**)&base_kg, g_base_kg);
    cudaGetSymbolAddress((void**)&off_kg, g_off_kg);
    cudaGetSymbolAddress((void**)&ssrc_kg, g_ssrc_kg);
    cudaGetSymbolAddress((void**)&bsum, g_bsum);
    cudaGetSymbolAddress((void**)&boff, g_boff);

    float* S0 = stats;
    float* S1 = stats + 2048;
    float* S2 = stats + 4096;
    float* S3 = stats + 6144;
    float* S4 = stats + 8192;
    float* S5 = stats + 10240;
    float* S6 = stats + 12288;
#define MEAN(S) ((S) + 1024)
#define RSTD(S) ((S) + 1536)

    const int* msrc = mol_ei;
    const int* mdst = mol_ei + E_MOL_C;
    const int* ksrc = kg_ei;
    const int* kdst = kg_ei + E_KG_C;

    // distinct weight-split regions (so splits can be done upfront, reused)
    __nv_bfloat16* B_fp1 = bsp;                     // 512*1024*2   = 1048576
    __nv_bfloat16* B_fp2 = B_fp1 + 1048576;         // 256*512*2    = 262144
    // reuse region A for gcn weights + rgcn (sequential stages):
    __nv_bfloat16* B_g1 = B_fp2 + 262144;           // 128*64*2     = 16384
    __nv_bfloat16* B_g2 = B_g1 + 16384;             // 256*128*2    = 65536
    // rg_w1 (256*2048*2 = 1048576) overlaps B_fp1 region? NO — keep separate budget:
    // total g_bsplit = 2M + 64K elems. Layout: fp1(1M) fp2(256K) g1(16K) g2(64K) = 1376256
    // remaining = 2097152+65536-1376256 = 786432 -> not enough for rg_w1(1M)+root1(128K)+w2(512K)+root2(64K)+lin1(16K)
    // => reuse B_fp1 region for rg_w1 after fp GEMMs are done.
    __nv_bfloat16* B_rgw1 = B_fp1;                  // 1048576 (reuse)
    __nv_bfloat16* B_root1 = B_fp2;                 // 256*256*2 = 131072 (reuse, fits 262144)
    __nv_bfloat16* B_rgw2 = B_g2 + 65536;           // 8*128*256*2 = 524288
    __nv_bfloat16* B_root2 = B_rgw2 + 524288;       // 128*256*2 = 65536
    __nv_bfloat16* B_lin1 = B_root2 + 65536;        // 64*128*2 = 16384

    zero4_kernel<<<cdiv(7 * 2048 / 4, 256), 256>>>((float4*)stats, 7 * 2048 / 4);

    // ---- CSR build ----
    const int NB_MOL = (N_MOL + 4095) / 4096;
    const int NB_KG = (NKEY_KG + 4095) / 4096;
    zero_int<<<cdiv(N_MOL, 256), 256>>>(hist_mol, N_MOL);
    hist_mol_k<<<cdiv(E_MOL_C, 256), 256>>>(hist_mol, mdst, E_MOL_C);
    scan_blk<<<NB_MOL, 1024>>>(hist_mol, base_mol, bsum, N_MOL);
    scan_bsum<<<1, 32>>>(bsum, boff, NB_MOL);
    scan_add<<<cdiv(N_MOL, 1024), 1024>>>(base_mol, off_mol, boff, N_MOL, NB_MOL);
    dinv_k<<<cdiv(N_MOL, 256), 256>>>(dinv, hist_mol, N_MOL);
    reorder_mol<<<cdiv(E_MOL_C, 256), 256>>>(msrc, mdst, off_mol, ssrc_mol, E_MOL_C);

    zero_int<<<cdiv(NKEY_KG, 256), 256>>>(hist_kg, NKEY_KG);
    hist_kg_k<<<cdiv(E_KG_C, 256), 256>>>(hist_kg, kdst, kg_et, E_KG_C);
    scan_blk<<<NB_KG, 1024>>>(hist_kg, base_kg, bsum, NKEY_KG);
    scan_bsum<<<1, 32>>>(bsum, boff, NB_KG);
    scan_add<<<cdiv(NKEY_KG, 1024), 1024>>>(base_kg, off_kg, boff, NKEY_KG, NB_KG);
    reorder_kg<<<cdiv(E_KG_C, 256), 256>>>(ksrc, kdst, kg_et, off_kg, ssrc_kg, E_KG_C);

    // ---- fp1: h1 = fp_data @ fp_w1 ----
    split_b2<<<dim3(cdiv((long)MLP_H * MLP_IN, 256), 1), 256>>>(fp_w1, B_fp1, 10, MLP_H);
    bgemm2<<<dim3(MLP_H / 128, N_DRUGS / 128), 256>>>(fp_data, B_fp1, h1,
        N_DRUGS, MLP_H, MLP_H, MLP_IN, 0, 0, 0, nullptr, nullptr);
    bn_partial<<<1184, 256>>>(h1, N_DRUGS, MLP_H, S0, S0 + 512);
    bn_finalize<<<cdiv(MLP_H, 128), 128>>>(N_DRUGS, MLP_H, S0, S0 + 512, MEAN(S0), RSTD(S0));

    // ---- fp2: fpb = bn_relu(h1) @ fp_w2 ----
    split_b2<<<dim3(cdiv((long)DFEAT * MLP_H, 256), 1), 256>>>(fp_w2, B_fp2, 9, DFEAT);
    bgemm2<<<dim3(DFEAT / 128, N_DRUGS / 128), 256>>>(h1, B_fp2, fpb,
        N_DRUGS, DFEAT, DFEAT, MLP_H, 0, 0, 0, MEAN(S0), RSTD(S0));
    bn_partial<<<1184, 256>>>(fpb, N_DRUGS, DFEAT, S1, S1 + 512);
    bn_finalize<<<cdiv(DFEAT, 128), 128>>>(N_DRUGS, DFEAT, S1, S1 + 512, MEAN(S1), RSTD(S1));

    // ---- conv1: bufB = agg(mol_x) @ gcn_w1 ----
    gcn_agg<<<N_MOL / 4, 256>>>(mol_x, ssrc_mol, base_mol, dinv, bufA, 6, nullptr, nullptr);
    split_b2<<<dim3(cdiv((long)GCN_H * GCN_IN, 256), 1), 256>>>(gcn_w1, B_g1, 6, GCN_H);
    bgemm2<<<dim3(1, N_MOL / 128), 256>>>(bufA, B_g1, bufB,
        N_MOL, GCN_H, GCN_H, GCN_IN, 0, 0, 0, nullptr, nullptr);
    bn_partial<<<1184, 256>>>(bufB, N_MOL, GCN_H, S2, S2 + 512);
    bn_finalize<<<cdiv(GCN_H, 128), 128>>>(N_MOL, GCN_H, S2, S2 + 512, MEAN(S2), RSTD(S2));

    // ---- conv2: bufA = agg(bn_relu(bufB)) @ gcn_w2 ----
    gcn_agg<<<N_MOL / 2, 256>>>(bufB, ssrc_mol, base_mol, dinv, bufC, 7, MEAN(S2), RSTD(S2));
    split_b2<<<dim3(cdiv((long)DFEAT * GCN_H, 256), 1), 256>>>(gcn_w2, B_g2, 7, DFEAT);
    bgemm2<<<dim3(DFEAT / 128, N_MOL / 128), 256>>>(bufC, B_g2, bufA,
        N_MOL, DFEAT, DFEAT, GCN_H, 0, 0, 0, nullptr, nullptr);
    bn_partial<<<1184, 256>>>(bufA, N_MOL, DFEAT, S3, S3 + 512);
    bn_finalize<<<cdiv(DFEAT, 128), 128>>>(N_MOL, DFEAT, S3, S3 + 512, MEAN(S3), RSTD(S3));
    bn_pool<<<N_DRUGS, 256>>>(bufA, mol_batch, MEAN(S3), RSTD(S3), pool);

    // ---- attention fusion ----
    att_kernel<<<N_DRUGS, 128>>>(pool, fpb, MEAN(S1), RSTD(S1),
                                 att_w1, att_b1, att_w2, xkg, out + N_KG * 2);
    copy_kernel<<<cdiv((long)N_GENE * DFEAT / 4, 256), 256>>>(
        (float4*)(xkg + (long)N_DRUGS * DFEAT), (const float4*)gene_emb, (long)N_GENE * DFEAT / 4);

    // ---- RGCN layer 1: agg = x@root1 ; agg += AGG @ W1stack ----
    rgcn_agg1<<<N_KG, 256>>>(xkg, ssrc_kg, base_kg, hr);
    split_b2<<<dim3(cdiv((long)DIM1 * DFEAT, 256), 1), 256>>>(rg_root1, B_root1, 8, DIM1);
    bgemm2<<<dim3(DIM1 / 128, cdiv(N_KG, 128)), 256>>>(xkg, B_root1, agg,
        N_KG, DIM1, DIM1, DFEAT, 0, 0, 0, nullptr, nullptr);
    split_b2<<<dim3(cdiv((long)DIM1 * 2048, 256), 1), 256>>>(rg_w1, B_rgw1, 11, DIM1);
    bgemm2<<<dim3(DIM1 / 128, cdiv(N_KG, 128)), 256>>>(hr, B_rgw1, agg,
        N_KG, DIM1, DIM1, 2048, 0, 0, 1, nullptr, nullptr);
    bn_partial<<<1184, 256>>>(agg, N_KG, DIM1, S4, S4 + 512);
    bn_finalize<<<cdiv(DIM1, 128), 128>>>(N_KG, DIM1, S4, S4 + 512, MEAN(S4), RSTD(S4));

    // ---- RGCN layer 2: hr[r] = bn_relu(agg) @ w2[r] ; xkg = bn_relu(agg)@root2 + agg2 ----
    split_b2<<<dim3(cdiv((long)DIM2 * DIM1, 256), R_REL), 256>>>(rg_w2, B_rgw2, 8, DIM2);
    bgemm2<<<dim3(1, cdiv(N_KG, 128), R_REL), 256>>>(agg, B_rgw2, hr,
        N_KG, DIM2, DIM2, DIM1, 0, (long)N_KG * DIM2, 0, MEAN(S4), RSTD(S4));
    split_b2<<<dim3(cdiv((long)DIM2 * DIM1, 256), 1), 256>>>(rg_root2, B_root2, 8, DIM2);
    bgemm2<<<dim3(1, cdiv(N_KG, 128)), 256>>>(agg, B_root2, xkg,
        N_KG, DIM2, DIM2, DIM1, 0, 0, 0, MEAN(S4), RSTD(S4));
    rgcn_agg2<<<cdiv(N_KG, 2), 256>>>(hr, ssrc_kg, base_kg, xkg);
    bn_partial<<<1184, 256>>>(xkg, N_KG, DIM2, S5, S5 + 512);
    bn_finalize<<<cdiv(DIM2, 128), 128>>>(N_KG, DIM2, S5, S5 + 512, MEAN(S5), RSTD(S5));

    // ---- lin1: x3 = bn_relu(xkg) @ lin1_w ----
    split_b2<<<dim3(cdiv((long)DIM3 * DIM2, 256), 1), 256>>>(lin1_w, B_lin1, 7, DIM3);
    bgemm2<<<dim3(1, cdiv(N_KG, 128)), 256>>>(xkg, B_lin1, x3,
        N_KG, DIM3, DIM3, DIM2, 0, 0, 0, MEAN(S5), RSTD(S5));
    bn_partial<<<1184, 256>>>(x3, N_KG, DIM3, S6, S6 + 512);
    bn_finalize<<<1, 128>>>(N_KG, DIM3, S6, S6 + 512, MEAN(S6), RSTD(S6));

    // ---- lin2 + log_softmax ----
    lin2_k<<<cdiv(N_KG, 128), 128>>>(x3, MEAN(S6), RSTD(S6), lin2_w, lin2_b, out);
}

// round 12
// speedup vs baseline: 1.4142x; 1.1673x over previous
#include <cuda_runtime.h>
#include <cuda_bf16.h>
#include <cstdint>
#include <math.h>

#define N_DRUGS 4096
#define N_GENE  5414
#define N_KG    9510
#define N_MOL   131072
#define E_MOL_C 524288
#define E_KG_C  524288
#define R_REL   8
#define MLP_IN  1024
#define MLP_H   512
#define DFEAT   256
#define GCN_IN  64
#define GCN_H   128
#define DIM1    256
#define DIM2    128
#define DIM3    64
#define EPSV    1e-5f
#define NKEY_KG (N_KG * R_REL)

// ---------------- scratch ----------------
__device__ __align__(16) float g_h1[N_DRUGS * MLP_H];
__device__ __align__(16) float g_fp[N_DRUGS * DFEAT];
__device__ __align__(16) float g_bufA[(long)N_MOL * DFEAT];
__device__ __align__(16) float g_bufB[(long)N_MOL * DFEAT];
__device__ __align__(16) float g_bufC[(long)N_MOL * DFEAT];
__device__ __align__(16) float g_dinv[N_MOL];
__device__ __align__(16) float g_pool[N_DRUGS * DFEAT];
__device__ __align__(16) float g_xkg[N_KG * DFEAT];
__device__ __align__(16) float g_hr[(long)R_REL * N_KG * DFEAT];   // also AGG [N_KG, 2048]
__device__ __align__(16) float g_agg[N_KG * DFEAT];
__device__ __align__(16) float g_x3[N_KG * DIM3];
__device__ __align__(16) float g_stats[7 * 2048];
// bf16 split weight planes: per z, [hi N*K | lo N*K]
__device__ __align__(16) __nv_bfloat16 g_bsplit[2 * 1024 * 1024 + 65536];
// CSR scratch
__device__ int g_hist_mol[N_MOL];
__device__ int g_base_mol[N_MOL + 1];
__device__ int g_off_mol[N_MOL];
__device__ int g_ssrc_mol[E_MOL_C];
__device__ int g_hist_kg[NKEY_KG];
__device__ int g_base_kg[NKEY_KG + 1];
__device__ int g_off_kg[NKEY_KG];
__device__ int g_ssrc_kg[E_KG_C];
__device__ int g_bsum[64];
__device__ int g_boff[65];

// ---------------- warp-MMA helpers (baseline PTX, sm_80+) ----------------
__device__ __forceinline__ uint32_t smem_to_u32(const void* p) {
    uint32_t a;
    asm("{ .reg .u64 t; cvta.to.shared.u64 t, %1; cvt.u32.u64 %0, t; }" : "=r"(a) : "l"(p));
    return a;
}
__device__ __forceinline__ void ldmatrix_x4(uint32_t* r, uint32_t addr) {
    asm volatile("ldmatrix.sync.aligned.m8n8.x4.shared.b16 {%0,%1,%2,%3}, [%4];"
                 : "=r"(r[0]), "=r"(r[1]), "=r"(r[2]), "=r"(r[3]) : "r"(addr));
}
__device__ __forceinline__ void mma_bf16(float* d, const uint32_t* a, uint32_t b0, uint32_t b1) {
    asm volatile("mma.sync.aligned.m16n8k16.row.col.f32.bf16.bf16.f32 "
                 "{%0,%1,%2,%3}, {%4,%5,%6,%7}, {%8,%9}, {%0,%1,%2,%3};"
                 : "+f"(d[0]), "+f"(d[1]), "+f"(d[2]), "+f"(d[3])
                 : "r"(a[0]), "r"(a[1]), "r"(a[2]), "r"(a[3]), "r"(b0), "r"(b1));
}

// ---------------- misc helpers ----------------
__device__ __forceinline__ float4 abn_apply4(float4 v, const float* m, const float* r, int k) {
    v.x = fmaxf((v.x - m[k + 0]) * r[k + 0], 0.f);
    v.y = fmaxf((v.y - m[k + 1]) * r[k + 1], 0.f);
    v.z = fmaxf((v.z - m[k + 2]) * r[k + 2], 0.f);
    v.w = fmaxf((v.w - m[k + 3]) * r[k + 3], 0.f);
    return v;
}

// ---------------- utility kernels ----------------
__global__ void zero4_kernel(float4* p, long n4) {
    long i = (long)blockIdx.x * blockDim.x + threadIdx.x;
    if (i < n4) p[i] = make_float4(0.f, 0.f, 0.f, 0.f);
}
__global__ void zero_int(int* p, int n) {
    int i = blockIdx.x * blockDim.x + threadIdx.x;
    if (i < n) p[i] = 0;
}
__global__ void copy_kernel(float4* dst, const float4* src, long n4) {
    long i = (long)blockIdx.x * blockDim.x + threadIdx.x;
    if (i < n4) dst[i] = src[i];
}

// ---------------- bf16 weight split: W[z][K][N] fp32 -> per z planes [hi NxK | lo NxK] ----------------
__global__ void split_b2(const float* __restrict__ W, __nv_bfloat16* __restrict__ Y,
                         int logK, int N) {
    int z = blockIdx.y;
    int K = 1 << logK;
    long total = (long)N << logK;
    long i = (long)blockIdx.x * blockDim.x + threadIdx.x;
    if (i >= total) return;
    int n = (int)(i >> logK);
    int k = (int)(i & (K - 1));
    float v = W[((long)z * K + k) * N + n];
    __nv_bfloat16 h = __float2bfloat16(v);
    __nv_bfloat16 l = __float2bfloat16(v - __bfloat162float(h));
    __nv_bfloat16* base = Y + (long)z * 2 * total;
    base[(long)n * K + k] = h;
    base[total + (long)n * K + k] = l;
}

// ---------------- HMMA split-fp32 GEMM, double-buffered, fused BN-A + fused stats ----------------
// C[M,ldc] (+)= A[M,K]fp32 @ Bsp[N,K]^T ; 3-term AhBh+AhBl+AlBh, fp32 accum.
// Dynamic smem: 4 planes x 2 bufs x 128x40 bf16 = 81920 B.
#define PL 5120  // elems per plane-buffer
__global__ void __launch_bounds__(256)
bgemm2(const float* __restrict__ A, const __nv_bfloat16* __restrict__ Bsp,
       float* __restrict__ C, int M, int N, int ldc, int K,
       long sA, long sC, int addC,
       const float* __restrict__ abn_mean, const float* __restrict__ abn_rstd,
       float* stat_sum, float* stat_sq) {
    extern __shared__ __nv_bfloat16 dsm[];
    __nv_bfloat16* AhP = dsm;             // [2][128][40]
    __nv_bfloat16* AlP = dsm + 2 * PL;
    __nv_bfloat16* BhP = dsm + 4 * PL;
    __nv_bfloat16* BlP = dsm + 6 * PL;
    int tid = threadIdx.x, wid = tid >> 5, lane = tid & 31;
    int row0 = blockIdx.y * 128, col0 = blockIdx.x * 128;
    const float* Az = A + (long)blockIdx.z * sA;
    long planeN = (long)N * K;
    const __nv_bfloat16* Bz = Bsp + (long)blockIdx.z * 2 * planeN;
    float* Cz = C + (long)blockIdx.z * sC;
    const bool dobn = (abn_mean != nullptr);
    int wr = wid >> 1, wc = wid & 1;
    int gid = lane >> 2, tig = lane & 3;
    int lrow = lane & 15;
    int lcol = (lane >> 4) << 3;

    float acc[2][8][4];
#pragma unroll
    for (int mt = 0; mt < 2; mt++)
#pragma unroll
        for (int nt = 0; nt < 8; nt++)
#pragma unroll
            for (int j = 0; j < 4; j++) acc[mt][nt][j] = 0.f;

    // A staging coords (4 iters), B coords (2 iters)
    int arA[4], acA[4];
#pragma unroll
    for (int it = 0; it < 4; it++) {
        int idx = tid + it * 256;
        arA[it] = idx >> 3;
        acA[it] = (idx & 7) << 2;
    }
    int rB[2], cB[2];
#pragma unroll
    for (int it = 0; it < 2; it++) {
        int idx = tid + it * 256;
        rB[it] = idx >> 2;
        cB[it] = (idx & 3) << 3;
    }

    int nchunks = K >> 5;
    // prologue: stage chunk 0 into buf 0
    {
#pragma unroll
        for (int it = 0; it < 4; it++) {
            int r = arA[it], c = acA[it];
            float4 v = make_float4(0.f, 0.f, 0.f, 0.f);
            if (row0 + r < M) {
                v = *(const float4*)(Az + (long)(row0 + r) * K + c);
                if (dobn) v = abn_apply4(v, abn_mean, abn_rstd, c);
            }
            float vf[4] = {v.x, v.y, v.z, v.w};
#pragma unroll
            for (int j = 0; j < 4; j++) {
                __nv_bfloat16 h = __float2bfloat16(vf[j]);
                AhP[r * 40 + c + j] = h;
                AlP[r * 40 + c + j] = __float2bfloat16(vf[j] - __bfloat162float(h));
            }
        }
#pragma unroll
        for (int it = 0; it < 2; it++) {
            int r = rB[it], cb = cB[it];
            int n = col0 + r;
            uint4 vh = make_uint4(0, 0, 0, 0), vl = make_uint4(0, 0, 0, 0);
            if (n < N) {
                vh = *(const uint4*)(Bz + (long)n * K + cb);
                vl = *(const uint4*)(Bz + planeN + (long)n * K + cb);
            }
            *(uint4*)&BhP[r * 40 + cb] = vh;
            *(uint4*)&BlP[r * 40 + cb] = vl;
        }
    }
    __syncthreads();

    int cur = 0;
    for (int t = 0; t < nchunks; t++) {
        float4 ra[4];
        uint4 rbh[2], rbl[2];
        bool more = (t + 1 < nchunks);
        if (more) {
            int k0 = (t + 1) << 5;
#pragma unroll
            for (int it = 0; it < 4; it++) {
                int r = arA[it], c = acA[it];
                ra[it] = make_float4(0.f, 0.f, 0.f, 0.f);
                if (row0 + r < M) {
                    ra[it] = *(const float4*)(Az + (long)(row0 + r) * K + k0 + c);
                    if (dobn) ra[it] = abn_apply4(ra[it], abn_mean, abn_rstd, k0 + c);
                }
            }
#pragma unroll
            for (int it = 0; it < 2; it++) {
                int r = rB[it], cb = cB[it];
                int n = col0 + r;
                rbh[it] = make_uint4(0, 0, 0, 0);
                rbl[it] = make_uint4(0, 0, 0, 0);
                if (n < N) {
                    rbh[it] = *(const uint4*)(Bz + (long)n * K + k0 + cb);
                    rbl[it] = *(const uint4*)(Bz + planeN + (long)n * K + k0 + cb);
                }
            }
        }
        // MMA on cur
        const __nv_bfloat16* Ahc = AhP + cur * PL;
        const __nv_bfloat16* Alc = AlP + cur * PL;
        const __nv_bfloat16* Bhc = BhP + cur * PL;
        const __nv_bfloat16* Blc = BlP + cur * PL;
#pragma unroll
        for (int ks = 0; ks < 2; ks++) {
            int kk = ks * 16;
            uint32_t ah[2][4], al[2][4];
#pragma unroll
            for (int mt = 0; mt < 2; mt++) {
                int r = wr * 32 + mt * 16 + lrow;
                ldmatrix_x4(ah[mt], smem_to_u32(&Ahc[r * 40 + kk + lcol]));
                ldmatrix_x4(al[mt], smem_to_u32(&Alc[r * 40 + kk + lcol]));
            }
#pragma unroll
            for (int nb = 0; nb < 4; nb++) {
                int r = wc * 64 + nb * 16 + lrow;
                uint32_t bh[4], bl[4];
                ldmatrix_x4(bh, smem_to_u32(&Bhc[r * 40 + kk + lcol]));
                ldmatrix_x4(bl, smem_to_u32(&Blc[r * 40 + kk + lcol]));
#pragma unroll
                for (int mt = 0; mt < 2; mt++) {
                    float* a0 = acc[mt][2 * nb + 0];
                    float* a1 = acc[mt][2 * nb + 1];
                    mma_bf16(a0, ah[mt], bh[0], bh[2]);
                    mma_bf16(a1, ah[mt], bh[1], bh[3]);
                    mma_bf16(a0, ah[mt], bl[0], bl[2]);
                    mma_bf16(a1, ah[mt], bl[1], bl[3]);
                    mma_bf16(a0, al[mt], bh[0], bh[2]);
                    mma_bf16(a1, al[mt], bh[1], bh[3]);
                }
            }
        }
        if (more) {
            int nb = cur ^ 1;
            __nv_bfloat16* Ahn = AhP + nb * PL;
            __nv_bfloat16* Aln = AlP + nb * PL;
#pragma unroll
            for (int it = 0; it < 4; it++) {
                int r = arA[it], c = acA[it];
                float vf[4] = {ra[it].x, ra[it].y, ra[it].z, ra[it].w};
#pragma unroll
                for (int j = 0; j < 4; j++) {
                    __nv_bfloat16 h = __float2bfloat16(vf[j]);
                    Ahn[r * 40 + c + j] = h;
                    Aln[r * 40 + c + j] = __float2bfloat16(vf[j] - __bfloat162float(h));
                }
            }
#pragma unroll
            for (int it = 0; it < 2; it++) {
                int r = rB[it], cb = cB[it];
                *(uint4*)&BhP[nb * PL + r * 40 + cb] = rbh[it];
                *(uint4*)&BlP[nb * PL + r * 40 + cb] = rbl[it];
            }
            __syncthreads();
            cur = nb;
        }
    }
    // epilogue: store C
#pragma unroll
    for (int mt = 0; mt < 2; mt++) {
        int r0 = row0 + wr * 32 + mt * 16 + gid;
#pragma unroll
        for (int nt = 0; nt < 8; nt++) {
            int c = col0 + wc * 64 + nt * 8 + 2 * tig;
            if (c < N) {
                if (r0 < M) {
                    float* p = Cz + (long)r0 * ldc + c;
                    if (addC) { p[0] += acc[mt][nt][0]; p[1] += acc[mt][nt][1]; }
                    else      { p[0]  = acc[mt][nt][0]; p[1]  = acc[mt][nt][1]; }
                }
                if (r0 + 8 < M) {
                    float* p = Cz + (long)(r0 + 8) * ldc + c;
                    if (addC) { p[0] += acc[mt][nt][2]; p[1] += acc[mt][nt][3]; }
                    else      { p[0]  = acc[mt][nt][2]; p[1]  = acc[mt][nt][3]; }
                }
            }
        }
    }
    // fused BN stats (col sums / sumsq); padded rows contribute exact zeros
    if (stat_sum != nullptr) {
        __syncthreads();
        float* ss = (float*)dsm;        // [4][128]
        float* sq = ss + 512;           // [4][128]
        float cs[8][2], cq[8][2];
#pragma unroll
        for (int nt = 0; nt < 8; nt++) {
#pragma unroll
            for (int w = 0; w < 2; w++) {
                float s = acc[0][nt][w] + acc[0][nt][w + 2] + acc[1][nt][w] + acc[1][nt][w + 2];
                float q = acc[0][nt][w] * acc[0][nt][w] + acc[0][nt][w + 2] * acc[0][nt][w + 2] +
                          acc[1][nt][w] * acc[1][nt][w] + acc[1][nt][w + 2] * acc[1][nt][w + 2];
                cs[nt][w] = s;
                cq[nt][w] = q;
            }
        }
#pragma unroll
        for (int o = 4; o <= 16; o <<= 1) {
#pragma unroll
            for (int nt = 0; nt < 8; nt++) {
#pragma unroll
                for (int w = 0; w < 2; w++) {
                    cs[nt][w] += __shfl_xor_sync(0xffffffffu, cs[nt][w], o);
                    cq[nt][w] += __shfl_xor_sync(0xffffffffu, cq[nt][w], o);
                }
            }
        }
        if (gid == 0) {
#pragma unroll
            for (int nt = 0; nt < 8; nt++) {
#pragma unroll
                for (int w = 0; w < 2; w++) {
                    int cl = wc * 64 + nt * 8 + 2 * tig + w;
                    ss[wr * 128 + cl] = cs[nt][w];
                    sq[wr * 128 + cl] = cq[nt][w];
                }
            }
        }
        __syncthreads();
        if (tid < 128) {
            int c = col0 + tid;
            if (c < N) {
                float a = ss[tid] + ss[128 + tid] + ss[256 + tid] + ss[384 + tid];
                float b = sq[tid] + sq[128 + tid] + sq[256 + tid] + sq[384 + tid];
                atomicAdd(&stat_sum[c], a);
                atomicAdd(&stat_sq[c], b);
            }
        }
    }
}

// ---------------- CSR build ----------------
__global__ void hist_mol_k(int* hist, const int* __restrict__ dst, int E) {
    int e = blockIdx.x * blockDim.x + threadIdx.x;
    if (e < E) atomicAdd(&hist[dst[e]], 1);
}
__global__ void hist_kg_k(int* hist, const int* __restrict__ dst, const int* __restrict__ et, int E) {
    int e = blockIdx.x * blockDim.x + threadIdx.x;
    if (e < E) atomicAdd(&hist[dst[e] * R_REL + et[e]], 1);
}
__global__ void scan_blk(const int* __restrict__ hist, int* __restrict__ base,
                         int* __restrict__ bsum, int n) {
    __shared__ int wsum[32];
    int b = blockIdx.x;
    int t = threadIdx.x, lane = t & 31, wid = t >> 5;
    int i0 = b * 4096 + t * 4;
    int v0 = (i0 < n) ? hist[i0] : 0;
    int v1 = (i0 + 1 < n) ? hist[i0 + 1] : 0;
    int v2 = (i0 + 2 < n) ? hist[i0 + 2] : 0;
    int v3 = (i0 + 3 < n) ? hist[i0 + 3] : 0;
    int s = v0 + v1 + v2 + v3;
    int sc = s;
#pragma unroll
    for (int o = 1; o < 32; o <<= 1) {
        int u = __shfl_up_sync(0xffffffffu, sc, o);
        if (lane >= o) sc += u;
    }
    if (lane == 31) wsum[wid] = sc;
    __syncthreads();
    if (wid == 0) {
        int w = wsum[lane];
        int wc = w;
#pragma unroll
        for (int o = 1; o < 32; o <<= 1) {
            int u = __shfl_up_sync(0xffffffffu, wc, o);
            if (lane >= o) wc += u;
        }
        wsum[lane] = wc - w;
    }
    __syncthreads();
    int excl = wsum[wid] + (sc - s);
    if (i0 < n) base[i0] = excl;
    excl += v0;
    if (i0 + 1 < n) base[i0 + 1] = excl;
    excl += v1;
    if (i0 + 2 < n) base[i0 + 2] = excl;
    excl += v2;
    if (i0 + 3 < n) base[i0 + 3] = excl;
    if (t == 1023) bsum[b] = wsum[31] + sc;
}
__global__ void scan_bsum(const int* __restrict__ bsum, int* __restrict__ boff, int nb) {
    int t = threadIdx.x;
    int v = (t < nb) ? bsum[t] : 0;
    int sc = v;
#pragma unroll
    for (int o = 1; o < 32; o <<= 1) {
        int u = __shfl_up_sync(0xffffffffu, sc, o);
        if (t >= o) sc += u;
    }
    if (t < nb) boff[t] = sc - v;
    if (t == 31) boff[nb] = sc;
}
__global__ void scan_add(int* __restrict__ base, int* __restrict__ off,
                         const int* __restrict__ boff, int n, int nb) {
    int i = blockIdx.x * blockDim.x + threadIdx.x;
    if (i < n) {
        int v = base[i] + boff[i >> 12];
        base[i] = v;
        off[i] = v;
    }
    if (i == 0) base[n] = boff[nb];
}
__global__ void reorder_mol(const int* __restrict__ src, const int* __restrict__ dst,
                            int* off, int* ssrc, int E) {
    int e = blockIdx.x * blockDim.x + threadIdx.x;
    if (e < E) {
        int p = atomicAdd(&off[dst[e]], 1);
        ssrc[p] = src[e];
    }
}
__global__ void reorder_kg(const int* __restrict__ src, const int* __restrict__ dst,
                           const int* __restrict__ et, int* off, int* ssrc, int E) {
    int e = blockIdx.x * blockDim.x + threadIdx.x;
    if (e < E) {
        int p = atomicAdd(&off[dst[e] * R_REL + et[e]], 1);
        ssrc[p] = src[e];
    }
}
__global__ void dinv_k(float* dinv, const int* __restrict__ hist, int n) {
    int i = blockIdx.x * blockDim.x + threadIdx.x;
    if (i < n) dinv[i] = rsqrtf((float)hist[i] + 1.0f);
}

// ---------------- GCN aggregation ----------------
__global__ void gcn_agg(const float* __restrict__ x, const int* __restrict__ ssrc,
                        const int* __restrict__ base, const float* __restrict__ dinv,
                        float* __restrict__ out, int logF,
                        const float* __restrict__ bmean, const float* __restrict__ brstd) {
    int F = 1 << logF;
    int t = threadIdx.x & (F - 1);
    int local = threadIdx.x >> logF;
    int d = blockIdx.x * (256 >> logF) + local;
    bool dobn = (bmean != nullptr);
    float m = 0.f, rs = 1.f;
    if (dobn) { m = bmean[t]; rs = brstd[t]; }
    int s0 = base[d], s1 = base[d + 1];
    float a0 = 0.f, a1 = 0.f;
    int p = s0;
    for (; p + 1 < s1; p += 2) {
        int sA = ssrc[p], sB = ssrc[p + 1];
        float vA = (x[((long)sA << logF) + t] - m) * rs;
        float vB = (x[((long)sB << logF) + t] - m) * rs;
        if (dobn) { vA = fmaxf(vA, 0.f); vB = fmaxf(vB, 0.f); }
        a0 += dinv[sA] * vA;
        a1 += dinv[sB] * vB;
    }
    if (p < s1) {
        int sA = ssrc[p];
        float vA = (x[((long)sA << logF) + t] - m) * rs;
        if (dobn) vA = fmaxf(vA, 0.f);
        a0 += dinv[sA] * vA;
    }
    float dd = dinv[d];
    float vs = (x[((long)d << logF) + t] - m) * rs;
    if (dobn) vs = fmaxf(vs, 0.f);
    out[((long)d << logF) + t] = dd * (a0 + a1) + dd * dd * vs;
}

// ---------------- RGCN aggregation ----------------
__global__ void rgcn_agg1(const float* __restrict__ x, const int* __restrict__ ssrc,
                          const int* __restrict__ base, float* __restrict__ AGG) {
    int d = blockIdx.x;
    int t = threadIdx.x;  // 256
#pragma unroll
    for (int r = 0; r < R_REL; r++) {
        int k = d * R_REL + r;
        int s0 = base[k], s1 = base[k + 1];
        float a0 = 0.f, a1 = 0.f;
        int p = s0;
        for (; p + 1 < s1; p += 2) {
            a0 += x[(long)ssrc[p] * 256 + t];
            a1 += x[(long)ssrc[p + 1] * 256 + t];
        }
        if (p < s1) a0 += x[(long)ssrc[p] * 256 + t];
        float nrm = (s1 > s0) ? 1.0f / (float)(s1 - s0) : 0.0f;
        AGG[(long)d * 2048 + r * 256 + t] = (a0 + a1) * nrm;
    }
}
__global__ void rgcn_agg2(const float* __restrict__ hr, const int* __restrict__ ssrc,
                          const int* __restrict__ base, float* __restrict__ xkg) {
    int d = blockIdx.x * 2 + (threadIdx.x >> 7);
    int t = threadIdx.x & 127;
    float tot = 0.f;
#pragma unroll
    for (int r = 0; r < R_REL; r++) {
        int k = d * R_REL + r;
        int s0 = base[k], s1 = base[k + 1];
        float a0 = 0.f, a1 = 0.f;
        int p = s0;
        const float* hp = hr + (long)r * N_KG * 128;
        for (; p + 1 < s1; p += 2) {
            a0 += hp[(long)ssrc[p] * 128 + t];
            a1 += hp[(long)ssrc[p + 1] * 128 + t];
        }
        if (p < s1) a0 += hp[(long)ssrc[p] * 128 + t];
        if (s1 > s0) tot += (a0 + a1) / (float)(s1 - s0);
    }
    if (d < N_KG) xkg[(long)d * 128 + t] += tot;
}

// ---------------- BatchNorm stats ----------------
__global__ void bn_partial(const float* __restrict__ X, int M, int F,
                           float* __restrict__ colsum, float* __restrict__ colsq) {
    float s0 = 0.f, s1 = 0.f, q0 = 0.f, q1 = 0.f;
    int f0 = threadIdx.x, f1 = threadIdx.x + 256;
    for (int r = blockIdx.x; r < M; r += gridDim.x) {
        const float* row = X + (long)r * F;
        if (f0 < F) { float v = row[f0]; s0 += v; q0 += v * v; }
        if (f1 < F) { float v = row[f1]; s1 += v; q1 += v * v; }
    }
    if (f0 < F) { atomicAdd(&colsum[f0], s0); atomicAdd(&colsq[f0], q0); }
    if (f1 < F) { atomicAdd(&colsum[f1], s1); atomicAdd(&colsq[f1], q1); }
}
__global__ void bn_finalize(int M, int F, const float* __restrict__ colsum,
                            const float* __restrict__ colsq,
                            float* __restrict__ mean, float* __restrict__ rstd) {
    int f = blockIdx.x * blockDim.x + threadIdx.x;
    if (f < F) {
        float m = colsum[f] / (float)M;
        float v = colsq[f] / (float)M - m * m;
        mean[f] = m;
        rstd[f] = rsqrtf(fmaxf(v, 0.0f) + EPSV);
    }
}
__global__ void bn_pool(const float* __restrict__ X, const int* __restrict__ batch,
                        const float* __restrict__ mean, const float* __restrict__ rstd,
                        float* __restrict__ pool) {
    int g = blockIdx.x;
    int t = threadIdx.x;  // 256
    __shared__ int sh_lo, sh_hi;
    if (t == 0) {
        int lo = 0, hi = N_MOL;
        while (lo < hi) { int m = (lo + hi) >> 1; if (batch[m] < g) lo = m + 1; else hi = m; }
        sh_lo = lo;
        int lo2 = lo, hi2 = N_MOL;
        while (lo2 < hi2) { int m = (lo2 + hi2) >> 1; if (batch[m] <= g) lo2 = m + 1; else hi2 = m; }
        sh_hi = lo2;
    }
    __syncthreads();
    int lo = sh_lo, hi = sh_hi;
    float m = mean[t], rs = rstd[t];
    float acc = 0.f;
    for (int i = lo; i < hi; i++) {
        float v = (X[(long)i * 256 + t] - m) * rs;
        acc += fmaxf(v, 0.f);
    }
    float c = (float)(hi - lo);
    pool[(long)g * 256 + t] = acc / fmaxf(c, 1.0f);
}

// ---------------- attention fusion ----------------
__global__ void att_kernel(const float* __restrict__ pool,
                           const float* __restrict__ fp,
                           const float* __restrict__ fmean, const float* __restrict__ frstd,
                           const float* __restrict__ w1, const float* __restrict__ b1,
                           const float* __restrict__ w2, float* __restrict__ xkg,
                           float* __restrict__ beta_out) {
    int n = blockIdx.x;
    int tid = threadIdx.x;  // 128
    __shared__ float z0[256], z1[256];
    __shared__ float red0[4], red1[4];
    __shared__ float bsh[2];
    for (int i = tid; i < 256; i += 128) {
        z0[i] = pool[(long)n * 256 + i];
        z1[i] = fmaxf((fp[(long)n * 256 + i] - fmean[i]) * frstd[i], 0.f);
    }
    __syncthreads();
    float s0 = 0.f, s1 = 0.f;
#pragma unroll 4
    for (int d = 0; d < 256; d++) {
        float w = w1[d * 128 + tid];
        s0 += z0[d] * w;
        s1 += z1[d] * w;
    }
    float bb = b1[tid], ww = w2[tid];
    float t0 = tanhf(s0 + bb) * ww;
    float t1 = tanhf(s1 + bb) * ww;
#pragma unroll
    for (int o = 16; o > 0; o >>= 1) {
        t0 += __shfl_down_sync(0xffffffffu, t0, o);
        t1 += __shfl_down_sync(0xffffffffu, t1, o);
    }
    int wid = tid >> 5, lid = tid & 31;
    if (lid == 0) { red0[wid] = t0; red1[wid] = t1; }
    __syncthreads();
    if (tid == 0) {
        float a0 = red0[0] + red0[1] + red0[2] + red0[3];
        float a1 = red1[0] + red1[1] + red1[2] + red1[3];
        float m = fmaxf(a0, a1);
        float e0 = expf(a0 - m), e1 = expf(a1 - m);
        float inv = 1.0f / (e0 + e1);
        bsh[0] = e0 * inv; bsh[1] = e1 * inv;
        beta_out[2 * n] = e0 * inv;
        beta_out[2 * n + 1] = e1 * inv;
    }
    __syncthreads();
    float b0v = bsh[0], b1v = bsh[1];
    for (int i = tid; i < 256; i += 128)
        xkg[(long)n * 256 + i] = b0v * z0[i] + b1v * z1[i];
}

// ---------------- final head ----------------
__global__ void lin2_k(const float* __restrict__ x,
                       const float* __restrict__ mean, const float* __restrict__ rstd,
                       const float* __restrict__ w, const float* __restrict__ b,
                       float* __restrict__ out) {
    int row = blockIdx.x * blockDim.x + threadIdx.x;
    if (row >= N_KG) return;
    float l0 = b[0], l1 = b[1];
    const float* xr = x + (long)row * 64;
#pragma unroll
    for (int d = 0; d < 64; d++) {
        float v = fmaxf((xr[d] - mean[d]) * rstd[d], 0.f);
        l0 += v * w[2 * d];
        l1 += v * w[2 * d + 1];
    }
    float m = fmaxf(l0, l1);
    float lse = m + logf(expf(l0 - m) + expf(l1 - m));
    out[2 * row] = l0 - lse;
    out[2 * row + 1] = l1 - lse;
}

// ---------------- host driver ----------------
static inline int cdiv(long a, long b) { return (int)((a + b - 1) / b); }
#define BG_SMEM 81920

extern "C" void kernel_launch(void* const* d_in, const int* in_sizes, int n_in,
                              void* d_out, int out_size) {
    const float* fp_data = (const float*)d_in[0];
    const float* mol_x   = (const float*)d_in[1];
    const int*   mol_batch = (const int*)d_in[2];
    const int*   mol_ei  = (const int*)d_in[3];
    const int*   kg_ei   = (const int*)d_in[4];
    const int*   kg_et   = (const int*)d_in[5];
    const float* fp_w1   = (const float*)d_in[6];
    const float* fp_w2   = (const float*)d_in[8];
    const float* gcn_w1  = (const float*)d_in[10];
    const float* gcn_w2  = (const float*)d_in[12];
    const float* att_w1  = (const float*)d_in[14];
    const float* att_b1  = (const float*)d_in[15];
    const float* att_w2  = (const float*)d_in[16];
    const float* gene_emb = (const float*)d_in[17];
    const float* rg_w1   = (const float*)d_in[18];
    const float* rg_root1 = (const float*)d_in[19];
    const float* rg_w2   = (const float*)d_in[21];
    const float* rg_root2 = (const float*)d_in[22];
    const float* lin1_w  = (const float*)d_in[24];
    const float* lin2_w  = (const float*)d_in[26];
    const float* lin2_b  = (const float*)d_in[27];
    float* out = (float*)d_out;

    static int smem_set = 0;
    if (!smem_set) {
        cudaFuncSetAttribute(bgemm2, cudaFuncAttributeMaxDynamicSharedMemorySize, BG_SMEM);
        smem_set = 1;
    }

    float *h1, *fpb, *bufA, *bufB, *bufC, *dinv, *pool, *xkg, *hr, *agg, *x3, *stats;
    __nv_bfloat16* bsp;
    int *hist_mol, *base_mol, *off_mol, *ssrc_mol, *hist_kg, *base_kg, *off_kg, *ssrc_kg;
    int *bsum, *boff;
    cudaGetSymbolAddress((void**)&h1, g_h1);
    cudaGetSymbolAddress((void**)&fpb, g_fp);
    cudaGetSymbolAddress((void**)&bufA, g_bufA);
    cudaGetSymbolAddress((void**)&bufB, g_bufB);
    cudaGetSymbolAddress((void**)&bufC, g_bufC);
    cudaGetSymbolAddress((void**)&dinv, g_dinv);
    cudaGetSymbolAddress((void**)&pool, g_pool);
    cudaGetSymbolAddress((void**)&xkg, g_xkg);
    cudaGetSymbolAddress((void**)&hr, g_hr);
    cudaGetSymbolAddress((void**)&agg, g_agg);
    cudaGetSymbolAddress((void**)&x3, g_x3);
    cudaGetSymbolAddress((void**)&stats, g_stats);
    cudaGetSymbolAddress((void**)&bsp, g_bsplit);
    cudaGetSymbolAddress((void**)&hist_mol, g_hist_mol);
    cudaGetSymbolAddress((void**)&base_mol, g_base_mol);
    cudaGetSymbolAddress((void**)&off_mol, g_off_mol);
    cudaGetSymbolAddress((void**)&ssrc_mol, g_ssrc_mol);
    cudaGetSymbolAddress((void**)&hist_kg, g_hist_kg);
    cudaGetSymbolAddress((void**)&base_kg, g_base_kg);
    cudaGetSymbolAddress((void**)&off_kg, g_off_kg);
    cudaGetSymbolAddress((void**)&ssrc_kg, g_ssrc_kg);
    cudaGetSymbolAddress((void**)&bsum, g_bsum);
    cudaGetSymbolAddress((void**)&boff, g_boff);

    float* S0 = stats;
    float* S1 = stats + 2048;
    float* S2 = stats + 4096;
    float* S3 = stats + 6144;
    float* S4 = stats + 8192;
    float* S5 = stats + 10240;
    float* S6 = stats + 12288;
#define MEAN(S) ((S) + 1024)
#define RSTD(S) ((S) + 1536)

    const int* msrc = mol_ei;
    const int* mdst = mol_ei + E_MOL_C;
    const int* ksrc = kg_ei;
    const int* kdst = kg_ei + E_KG_C;

    __nv_bfloat16* B_fp1 = bsp;
    __nv_bfloat16* B_fp2 = B_fp1 + 1048576;
    __nv_bfloat16* B_g1 = B_fp2 + 262144;
    __nv_bfloat16* B_g2 = B_g1 + 16384;
    __nv_bfloat16* B_rgw1 = B_fp1;   // reuse after fp GEMMs
    __nv_bfloat16* B_root1 = B_fp2;  // reuse
    __nv_bfloat16* B_rgw2 = B_g2 + 65536;
    __nv_bfloat16* B_root2 = B_rgw2 + 524288;
    __nv_bfloat16* B_lin1 = B_root2 + 65536;

    zero4_kernel<<<cdiv(7 * 2048 / 4, 256), 256>>>((float4*)stats, 7 * 2048 / 4);

    // ---- CSR build ----
    const int NB_MOL = (N_MOL + 4095) / 4096;
    const int NB_KG = (NKEY_KG + 4095) / 4096;
    zero_int<<<cdiv(N_MOL, 256), 256>>>(hist_mol, N_MOL);
    hist_mol_k<<<cdiv(E_MOL_C, 256), 256>>>(hist_mol, mdst, E_MOL_C);
    scan_blk<<<NB_MOL, 1024>>>(hist_mol, base_mol, bsum, N_MOL);
    scan_bsum<<<1, 32>>>(bsum, boff, NB_MOL);
    scan_add<<<cdiv(N_MOL, 1024), 1024>>>(base_mol, off_mol, boff, N_MOL, NB_MOL);
    dinv_k<<<cdiv(N_MOL, 256), 256>>>(dinv, hist_mol, N_MOL);
    reorder_mol<<<cdiv(E_MOL_C, 256), 256>>>(msrc, mdst, off_mol, ssrc_mol, E_MOL_C);

    zero_int<<<cdiv(NKEY_KG, 256), 256>>>(hist_kg, NKEY_KG);
    hist_kg_k<<<cdiv(E_KG_C, 256), 256>>>(hist_kg, kdst, kg_et, E_KG_C);
    scan_blk<<<NB_KG, 1024>>>(hist_kg, base_kg, bsum, NKEY_KG);
    scan_bsum<<<1, 32>>>(bsum, boff, NB_KG);
    scan_add<<<cdiv(NKEY_KG, 1024), 1024>>>(base_kg, off_kg, boff, NKEY_KG, NB_KG);
    reorder_kg<<<cdiv(E_KG_C, 256), 256>>>(ksrc, kdst, kg_et, off_kg, ssrc_kg, E_KG_C);

    // ---- fp1: h1 = fp_data @ fp_w1 (stats fused -> S0) ----
    split_b2<<<dim3(cdiv((long)MLP_H * MLP_IN, 256), 1), 256>>>(fp_w1, B_fp1, 10, MLP_H);
    bgemm2<<<dim3(MLP_H / 128, N_DRUGS / 128), 256, BG_SMEM>>>(fp_data, B_fp1, h1,
        N_DRUGS, MLP_H, MLP_H, MLP_IN, 0, 0, 0, nullptr, nullptr, S0, S0 + 512);
    bn_finalize<<<cdiv(MLP_H, 128), 128>>>(N_DRUGS, MLP_H, S0, S0 + 512, MEAN(S0), RSTD(S0));

    // ---- fp2: fpb = bn_relu(h1) @ fp_w2 (stats fused -> S1) ----
    split_b2<<<dim3(cdiv((long)DFEAT * MLP_H, 256), 1), 256>>>(fp_w2, B_fp2, 9, DFEAT);
    bgemm2<<<dim3(DFEAT / 128, N_DRUGS / 128), 256, BG_SMEM>>>(h1, B_fp2, fpb,
        N_DRUGS, DFEAT, DFEAT, MLP_H, 0, 0, 0, MEAN(S0), RSTD(S0), S1, S1 + 512);
    bn_finalize<<<cdiv(DFEAT, 128), 128>>>(N_DRUGS, DFEAT, S1, S1 + 512, MEAN(S1), RSTD(S1));

    // ---- conv1: bufB = agg(mol_x) @ gcn_w1 (stats fused -> S2) ----
    gcn_agg<<<N_MOL / 4, 256>>>(mol_x, ssrc_mol, base_mol, dinv, bufA, 6, nullptr, nullptr);
    split_b2<<<dim3(cdiv((long)GCN_H * GCN_IN, 256), 1), 256>>>(gcn_w1, B_g1, 6, GCN_H);
    bgemm2<<<dim3(1, N_MOL / 128), 256, BG_SMEM>>>(bufA, B_g1, bufB,
        N_MOL, GCN_H, GCN_H, GCN_IN, 0, 0, 0, nullptr, nullptr, S2, S2 + 512);
    bn_finalize<<<cdiv(GCN_H, 128), 128>>>(N_MOL, GCN_H, S2, S2 + 512, MEAN(S2), RSTD(S2));

    // ---- conv2: bufA = agg(bn_relu(bufB)) @ gcn_w2 (stats fused -> S3) ----
    gcn_agg<<<N_MOL / 2, 256>>>(bufB, ssrc_mol, base_mol, dinv, bufC, 7, MEAN(S2), RSTD(S2));
    split_b2<<<dim3(cdiv((long)DFEAT * GCN_H, 256), 1), 256>>>(gcn_w2, B_g2, 7, DFEAT);
    bgemm2<<<dim3(DFEAT / 128, N_MOL / 128), 256, BG_SMEM>>>(bufC, B_g2, bufA,
        N_MOL, DFEAT, DFEAT, GCN_H, 0, 0, 0, nullptr, nullptr, S3, S3 + 512);
    bn_finalize<<<cdiv(DFEAT, 128), 128>>>(N_MOL, DFEAT, S3, S3 + 512, MEAN(S3), RSTD(S3));
    bn_pool<<<N_DRUGS, 256>>>(bufA, mol_batch, MEAN(S3), RSTD(S3), pool);

    // ---- attention fusion ----
    att_kernel<<<N_DRUGS, 128>>>(pool, fpb, MEAN(S1), RSTD(S1),
                                 att_w1, att_b1, att_w2, xkg, out + N_KG * 2);
    copy_kernel<<<cdiv((long)N_GENE * DFEAT / 4, 256), 256>>>(
        (float4*)(xkg + (long)N_DRUGS * DFEAT), (const float4*)gene_emb, (long)N_GENE * DFEAT / 4);

    // ---- RGCN layer 1: agg = x@root1 ; agg += AGG @ W1stack ----
    rgcn_agg1<<<N_KG, 256>>>(xkg, ssrc_kg, base_kg, hr);
    split_b2<<<dim3(cdiv((long)DIM1 * DFEAT, 256), 1), 256>>>(rg_root1, B_root1, 8, DIM1);
    bgemm2<<<dim3(DIM1 / 128, cdiv(N_KG, 128)), 256, BG_SMEM>>>(xkg, B_root1, agg,
        N_KG, DIM1, DIM1, DFEAT, 0, 0, 0, nullptr, nullptr, nullptr, nullptr);
    split_b2<<<dim3(cdiv((long)DIM1 * 2048, 256), 1), 256>>>(rg_w1, B_rgw1, 11, DIM1);
    bgemm2<<<dim3(DIM1 / 128, cdiv(N_KG, 128)), 256, BG_SMEM>>>(hr, B_rgw1, agg,
        N_KG, DIM1, DIM1, 2048, 0, 0, 1, nullptr, nullptr, nullptr, nullptr);
    bn_partial<<<1184, 256>>>(agg, N_KG, DIM1, S4, S4 + 512);
    bn_finalize<<<cdiv(DIM1, 128), 128>>>(N_KG, DIM1, S4, S4 + 512, MEAN(S4), RSTD(S4));

    // ---- RGCN layer 2 ----
    split_b2<<<dim3(cdiv((long)DIM2 * DIM1, 256), R_REL), 256>>>(rg_w2, B_rgw2, 8, DIM2);
    bgemm2<<<dim3(1, cdiv(N_KG, 128), R_REL), 256, BG_SMEM>>>(agg, B_rgw2, hr,
        N_KG, DIM2, DIM2, DIM1, 0, (long)N_KG * DIM2, 0, MEAN(S4), RSTD(S4), nullptr, nullptr);
    split_b2<<<dim3(cdiv((long)DIM2 * DIM1, 256), 1), 256>>>(rg_root2, B_root2, 8, DIM2);
    bgemm2<<<dim3(1, cdiv(N_KG, 128)), 256, BG_SMEM>>>(agg, B_root2, xkg,
        N_KG, DIM2, DIM2, DIM1, 0, 0, 0, MEAN(S4), RSTD(S4), nullptr, nullptr);
    rgcn_agg2<<<cdiv(N_KG, 2), 256>>>(hr, ssrc_kg, base_kg, xkg);
    bn_partial<<<1184, 256>>>(xkg, N_KG, DIM2, S5, S5 + 512);
    bn_finalize<<<cdiv(DIM2, 128), 128>>>(N_KG, DIM2, S5, S5 + 512, MEAN(S5), RSTD(S5));

    // ---- lin1: x3 = bn_relu(xkg) @ lin1_w (stats fused -> S6) ----
    split_b2<<<dim3(cdiv((long)DIM3 * DIM2, 256), 1), 256>>>(lin1_w, B_lin1, 7, DIM3);
    bgemm2<<<dim3(1, cdiv(N_KG, 128)), 256, BG_SMEM>>>(xkg, B_lin1, x3,
        N_KG, DIM3, DIM3, DIM2, 0, 0, 0, MEAN(S5), RSTD(S5), S6, S6 + 512);
    bn_finalize<<<1, 128>>>(N_KG, DIM3, S6, S6 + 512, MEAN(S6), RSTD(S6));

    // ---- lin2 + log_softmax ----
    lin2_k<<<cdiv(N_KG, 128), 128>>>(x3, MEAN(S6), RSTD(S6), lin2_w, lin2_b, out);
}